// round 11
// baseline (speedup 1.0000x reference)
#include <cuda_runtime.h>
#include <cuda_fp16.h>

#define D 64
#define MAXN 100000
#define MAXE 1250000
#define BN_EPS 1e-5f
#define TILE 128
#define AROWH 136
#define WROWH 72

__device__ __forceinline__ __half2 u2h2(unsigned u) { return *reinterpret_cast<__half2*>(&u); }
__device__ __forceinline__ unsigned h2u(__half2 h) { return *reinterpret_cast<unsigned*>(&h); }

// ---------------- static device scratch -------------------------------------
__device__ int   g_deg[MAXN];          // zero at module load; re-zeroed by scan1 every run
__device__ int   g_rowptr[MAXN + 1];
__device__ int   g_cursor[MAXN + 1];
__device__ int   g_blocksums[256];
__device__ int   g_srcsorted[MAXE];
__device__ __align__(16) __half g_xh[(size_t)MAXN * D];
__device__ __align__(16) __half g_hA[(size_t)MAXN * D];
__device__ __align__(16) __half g_hB[(size_t)MAXN * D];
__device__ __align__(16) float g_s0[D];
__device__ __align__(16) float g_q0[D];
__device__ __align__(16) float g_s1[D];
__device__ __align__(16) float g_q1[D];
__device__ __align__(16) float g_s2[D];
__device__ __align__(16) float g_q2[D];
__device__ unsigned g_bar_cnt;   // monotonic, never reset

// ---------------- grid barrier (monotonic counter, wrap-safe) ----------------
__device__ __forceinline__ void grid_bar() {
    __syncthreads();
    if (threadIdx.x == 0) {
        __threadfence();
        unsigned t = atomicAdd(&g_bar_cnt, 1u);
        unsigned target = t - (t % gridDim.x) + gridDim.x;
        if ((t % gridDim.x) != gridDim.x - 1) {
            volatile unsigned* p = &g_bar_cnt;
            while ((int)(*p - target) < 0) __nanosleep(64);
        }
        __threadfence();
    }
    __syncthreads();
}

// ---------------- K_csr: convert + hist | scan1 | scan23 | bucket ------------
#define CSR_BLOCKS 392
__global__ void __launch_bounds__(256) k_csr(
    const float* __restrict__ x, const int* __restrict__ ei,
    int N, int E, int NB, int total8)
{
    __shared__ int ish[256];
    int tid = threadIdx.x;
    int gtid = blockIdx.x * 256 + tid;
    int gstride = gridDim.x * 256;

    // ---- phase A: convert x -> fp16, zero stats, histogram ----
    for (int i = gtid; i < total8; i += gstride) {
        float4 a = ((const float4*)x)[i * 2];
        float4 b = ((const float4*)x)[i * 2 + 1];
        uint4 o;
        o.x = h2u(__floats2half2_rn(a.x, a.y));
        o.y = h2u(__floats2half2_rn(a.z, a.w));
        o.z = h2u(__floats2half2_rn(b.x, b.y));
        o.w = h2u(__floats2half2_rn(b.z, b.w));
        ((uint4*)g_xh)[i] = o;
    }
    if (blockIdx.x == 0 && tid < D) {
        g_s0[tid] = 0.f; g_q0[tid] = 0.f;
        g_s1[tid] = 0.f; g_q1[tid] = 0.f;
        g_s2[tid] = 0.f; g_q2[tid] = 0.f;
    }
    for (int e = gtid; e < E; e += gstride)
        atomicAdd(&g_deg[ei[E + e]], 1);
    grid_bar();

    // ---- phase B: scan1 (read deg, RE-ZERO deg for next run, local scan) ----
    if (blockIdx.x < NB) {
        int base = blockIdx.x * 1024 + tid * 4;
        int v0 = 0, v1 = 0, v2 = 0, v3 = 0;
        if (base + 0 < N) { v0 = g_deg[base + 0]; g_deg[base + 0] = 0; }
        if (base + 1 < N) { v1 = g_deg[base + 1]; g_deg[base + 1] = 0; }
        if (base + 2 < N) { v2 = g_deg[base + 2]; g_deg[base + 2] = 0; }
        if (base + 3 < N) { v3 = g_deg[base + 3]; g_deg[base + 3] = 0; }
        int t0 = v0, t1 = t0 + v1, t2 = t1 + v2, t3 = t2 + v3;
        ish[tid] = t3;
        __syncthreads();
        for (int off = 1; off < 256; off <<= 1) {
            int a = (tid >= off) ? ish[tid - off] : 0;
            __syncthreads();
            ish[tid] += a;
            __syncthreads();
        }
        int excl = ish[tid] - t3;
        if (base + 0 < N) g_rowptr[base + 1] = excl + t0;
        if (base + 1 < N) g_rowptr[base + 2] = excl + t1;
        if (base + 2 < N) g_rowptr[base + 3] = excl + t2;
        if (base + 3 < N) g_rowptr[base + 4] = excl + t3;
        if (tid == 255) g_blocksums[blockIdx.x] = ish[255];
    }
    grid_bar();

    // ---- phase C: scan23 (rescan blocksums, apply offset, fill cursor) ----
    if (blockIdx.x < NB) {
        int v = (tid < NB) ? g_blocksums[tid] : 0;
        ish[tid] = v;
        __syncthreads();
        for (int off = 1; off < 256; off <<= 1) {
            int a = (tid >= off) ? ish[tid - off] : 0;
            __syncthreads();
            ish[tid] += a;
            __syncthreads();
        }
        int off = (blockIdx.x == 0) ? 0 : ish[blockIdx.x - 1];
        int base = blockIdx.x * 1024 + tid * 4;
#pragma unroll
        for (int i = 0; i < 4; i++) {
            int idx = base + i;
            if (idx < N) {
                int val = g_rowptr[idx + 1] + off;
                g_rowptr[idx + 1] = val;
                if (idx + 1 < N) g_cursor[idx + 1] = val;
            }
        }
        if (blockIdx.x == 0 && tid == 0) { g_rowptr[0] = 0; g_cursor[0] = 0; }
    }
    grid_bar();

    // ---- phase D: bucket ----
    for (int e = gtid; e < E; e += gstride) {
        int d = ei[E + e];
        int pos = atomicAdd(&g_cursor[d], 1);
        g_srcsorted[pos] = ei[e];
    }
}

// ---------------- fused layer: per-tile gather into smem + MMA ---------------
#define SMEM_A_BYTES (128 * AROWH * 2)
#define SMEM_W_OFF   SMEM_A_BYTES
#define SMEM_F_OFF   (SMEM_A_BYTES + 128 * WROWH * 2)
#define SMEM_BYTES   (SMEM_F_OFF + 64 * 4 * 3 + 64 * 2 * 2)

template<int TF>
__global__ void __launch_bounds__(256) k_layer(
    const __half* __restrict__ x_src, __half* __restrict__ h_out,
    const float* __restrict__ Wrel, const float* __restrict__ brel,
    const float* __restrict__ Wroot,
    const float* __restrict__ ssum_in, const float* __restrict__ ssq_in,
    const float* __restrict__ gamma_p, const float* __restrict__ beta_p,
    float* __restrict__ ssum_out, float* __restrict__ ssq_out,
    float invN, int N)
{
    extern __shared__ char smemc[];
    __half* a_sh = (__half*)smemc;
    __half* w_sh = (__half*)(smemc + SMEM_W_OFF);
    float* s_bias = (float*)(smemc + SMEM_F_OFF);
    float* s_sum = s_bias + 64;
    float* s_sq  = s_sum + 64;
    __half* s_sch = (__half*)(s_sq + 64);
    __half* s_shh = s_sch + 64;

    int tid = threadIdx.x;
    int lane = tid & 31;
    int w = tid >> 5;
    int tile0 = blockIdx.x * TILE;

    // stage W (fp32 -> fp16)
    for (int i = tid; i < 1024; i += 256) {
        int k = i >> 4, n4 = (i & 15) * 4;
        float4 v = ((const float4*)Wrel)[i];
        uint2 hv;
        hv.x = h2u(__floats2half2_rn(v.x, v.y));
        hv.y = h2u(__floats2half2_rn(v.z, v.w));
        *(uint2*)(w_sh + k * WROWH + n4) = hv;
        float4 u = ((const float4*)Wroot)[i];
        uint2 hu;
        hu.x = h2u(__floats2half2_rn(u.x, u.y));
        hu.y = h2u(__floats2half2_rn(u.z, u.w));
        *(uint2*)(w_sh + (64 + k) * WROWH + n4) = hu;
    }
    if (tid < 64) {
        s_bias[tid] = brel[tid];
        s_sum[tid] = 0.f;
        s_sq[tid] = 0.f;
        if (TF) {
            float mean = ssum_in[tid] * invN;
            float var = fmaf(-mean, mean, ssq_in[tid] * invN);
            var = var < 0.f ? 0.f : var;
            float s = gamma_p[tid] * rsqrtf(var + BN_EPS);
            s_sch[tid] = __float2half_rn(s);
            s_shh[tid] = __float2half_rn(beta_p[tid] - mean * s);
        }
    }
    __syncthreads();

    // ---- gather phase: warp w fills rows 16w..16w+15 of a_sh = [msg | x] ----
    {
        int q = lane >> 3, c8 = lane & 7;
        __half2 sc2[4], sh2[4];
        if (TF) {
#pragma unroll
            for (int j = 0; j < 4; j++) {
                sc2[j] = ((const __half2*)s_sch)[c8 * 4 + j];
                sh2[j] = ((const __half2*)s_shh)[c8 * 4 + j];
            }
        }
        for (int j = 0; j < 16; j++) {
            int r = w * 16 + j;
            int node = tile0 + r;
            if (node < N) {
                // x row (lanes 0..7), BN+ReLU if TF
                if (lane < 8) {
                    uint4 raw = ((const uint4*)(x_src + (size_t)node * D))[c8];
                    if (TF) {
                        __half2 z = __float2half2_rn(0.f);
                        raw.x = h2u(__hmax2(__hfma2(u2h2(raw.x), sc2[0], sh2[0]), z));
                        raw.y = h2u(__hmax2(__hfma2(u2h2(raw.y), sc2[1], sh2[1]), z));
                        raw.z = h2u(__hmax2(__hfma2(u2h2(raw.z), sc2[2], sh2[2]), z));
                        raw.w = h2u(__hmax2(__hfma2(u2h2(raw.w), sc2[3], sh2[3]), z));
                    }
                    *(uint4*)(a_sh + r * AROWH + 64 + c8 * 8) = raw;
                }
                // neighbor accumulation (4 slots x 8 column-lanes)
                float acc[8];
#pragma unroll
                for (int t = 0; t < 8; t++) acc[t] = 0.f;
                int rs = g_rowptr[node], re = g_rowptr[node + 1];
                for (int base = rs; base < re; base += 32) {
                    int jj = base + lane;
                    int sj = (jj < re) ? g_srcsorted[jj] : 0;
                    int cnt = min(32, re - base);
                    for (int u = 0; u < cnt; u += 4) {
                        int i0 = u + q;
                        int s = __shfl_sync(0xffffffffu, sj, i0 & 31);
                        if (i0 < cnt) {
                            uint4 raw = *(const uint4*)(x_src + (size_t)s * D + c8 * 8);
                            __half2 v0 = u2h2(raw.x), v1 = u2h2(raw.y), v2 = u2h2(raw.z), v3 = u2h2(raw.w);
                            if (TF) {
                                __half2 z = __float2half2_rn(0.f);
                                v0 = __hmax2(__hfma2(v0, sc2[0], sh2[0]), z);
                                v1 = __hmax2(__hfma2(v1, sc2[1], sh2[1]), z);
                                v2 = __hmax2(__hfma2(v2, sc2[2], sh2[2]), z);
                                v3 = __hmax2(__hfma2(v3, sc2[3], sh2[3]), z);
                            }
                            float2 f0 = __half22float2(v0), f1 = __half22float2(v1);
                            float2 f2 = __half22float2(v2), f3 = __half22float2(v3);
                            acc[0] += f0.x; acc[1] += f0.y; acc[2] += f1.x; acc[3] += f1.y;
                            acc[4] += f2.x; acc[5] += f2.y; acc[6] += f3.x; acc[7] += f3.y;
                        }
                    }
                }
#pragma unroll
                for (int off = 8; off <= 16; off <<= 1)
#pragma unroll
                    for (int t = 0; t < 8; t++) acc[t] += __shfl_xor_sync(0xffffffffu, acc[t], off);
                if (lane < 8) {
                    uint4 o;
                    o.x = h2u(__floats2half2_rn(acc[0], acc[1]));
                    o.y = h2u(__floats2half2_rn(acc[2], acc[3]));
                    o.z = h2u(__floats2half2_rn(acc[4], acc[5]));
                    o.w = h2u(__floats2half2_rn(acc[6], acc[7]));
                    *(uint4*)(a_sh + r * AROWH + c8 * 8) = o;
                }
            } else {
                if (lane < 16)
                    *(uint4*)(a_sh + r * AROWH + lane * 8) = make_uint4(0u, 0u, 0u, 0u);
            }
        }
    }
    __syncthreads();

    // ---- MMA phase ----
    unsigned sbase = (unsigned)__cvta_generic_to_shared(smemc);
    unsigned a_addr = sbase + ((16 * w + (lane & 15)) * AROWH + ((lane >> 4) << 3)) * 2;
    unsigned b_addr = sbase + SMEM_W_OFF + ((lane & 15) * WROWH + ((lane >> 4) << 3)) * 2;
    int grp = lane >> 2, tig = lane & 3;

    float c[8][4];
#pragma unroll
    for (int nt = 0; nt < 8; nt++) {
        float b0 = s_bias[nt * 8 + tig * 2];
        float b1 = s_bias[nt * 8 + tig * 2 + 1];
        c[nt][0] = b0; c[nt][1] = b1; c[nt][2] = b0; c[nt][3] = b1;
    }

#pragma unroll
    for (int ks = 0; ks < 8; ks++) {
        unsigned a0, a1, a2, a3;
        asm volatile("ldmatrix.sync.aligned.m8n8.x4.shared.b16 {%0,%1,%2,%3}, [%4];"
                     : "=r"(a0), "=r"(a1), "=r"(a2), "=r"(a3)
                     : "r"(a_addr + ks * 32));
#pragma unroll
        for (int nt4 = 0; nt4 < 4; nt4++) {
            unsigned b0, b1, b2, b3;
            asm volatile("ldmatrix.sync.aligned.m8n8.x4.trans.shared.b16 {%0,%1,%2,%3}, [%4];"
                         : "=r"(b0), "=r"(b1), "=r"(b2), "=r"(b3)
                         : "r"(b_addr + ks * (16 * WROWH * 2) + nt4 * 32));
            asm volatile("mma.sync.aligned.m16n8k16.row.col.f32.f16.f16.f32 "
                         "{%0,%1,%2,%3}, {%4,%5,%6,%7}, {%8,%9}, {%0,%1,%2,%3};"
                         : "+f"(c[2 * nt4][0]), "+f"(c[2 * nt4][1]), "+f"(c[2 * nt4][2]), "+f"(c[2 * nt4][3])
                         : "r"(a0), "r"(a1), "r"(a2), "r"(a3), "r"(b0), "r"(b1));
            asm volatile("mma.sync.aligned.m16n8k16.row.col.f32.f16.f16.f32 "
                         "{%0,%1,%2,%3}, {%4,%5,%6,%7}, {%8,%9}, {%0,%1,%2,%3};"
                         : "+f"(c[2 * nt4 + 1][0]), "+f"(c[2 * nt4 + 1][1]), "+f"(c[2 * nt4 + 1][2]), "+f"(c[2 * nt4 + 1][3])
                         : "r"(a0), "r"(a1), "r"(a2), "r"(a3), "r"(b2), "r"(b3));
        }
    }

    // epilogue: store h (fp16) + BN stats
    float sl[16], ql[16];
#pragma unroll
    for (int i = 0; i < 16; i++) { sl[i] = 0.f; ql[i] = 0.f; }

    int row0 = tile0 + 16 * w + grp;
    int row1 = row0 + 8;
    bool v0 = row0 < N, v1 = row1 < N;
#pragma unroll
    for (int nt = 0; nt < 8; nt++) {
        int col = nt * 8 + tig * 2;
        if (v0) {
            *(unsigned*)(h_out + (size_t)row0 * D + col) = h2u(__floats2half2_rn(c[nt][0], c[nt][1]));
            sl[2 * nt]     += c[nt][0];
            ql[2 * nt]      = fmaf(c[nt][0], c[nt][0], ql[2 * nt]);
            sl[2 * nt + 1] += c[nt][1];
            ql[2 * nt + 1]  = fmaf(c[nt][1], c[nt][1], ql[2 * nt + 1]);
        }
        if (v1) {
            *(unsigned*)(h_out + (size_t)row1 * D + col) = h2u(__floats2half2_rn(c[nt][2], c[nt][3]));
            sl[2 * nt]     += c[nt][2];
            ql[2 * nt]      = fmaf(c[nt][2], c[nt][2], ql[2 * nt]);
            sl[2 * nt + 1] += c[nt][3];
            ql[2 * nt + 1]  = fmaf(c[nt][3], c[nt][3], ql[2 * nt + 1]);
        }
    }

#pragma unroll
    for (int off = 4; off <= 16; off <<= 1) {
#pragma unroll
        for (int i = 0; i < 16; i++) {
            sl[i] += __shfl_xor_sync(0xffffffffu, sl[i], off);
            ql[i] += __shfl_xor_sync(0xffffffffu, ql[i], off);
        }
    }
    if (lane < 4) {
#pragma unroll
        for (int nt = 0; nt < 8; nt++) {
            atomicAdd(&s_sum[nt * 8 + 2 * lane],     sl[2 * nt]);
            atomicAdd(&s_sum[nt * 8 + 2 * lane + 1], sl[2 * nt + 1]);
            atomicAdd(&s_sq[nt * 8 + 2 * lane],      ql[2 * nt]);
            atomicAdd(&s_sq[nt * 8 + 2 * lane + 1],  ql[2 * nt + 1]);
        }
    }
    __syncthreads();
    if (tid < 64) atomicAdd(&ssum_out[tid], s_sum[tid]);
    else if (tid < 128) atomicAdd(&ssq_out[tid - 64], s_sq[tid - 64]);
}

// ---------------- pooling + classifier (final BN+ReLU inline) ----------------
__global__ void __launch_bounds__(1024) k_pool(
    const __half* __restrict__ hfin, const int* __restrict__ batch, int N,
    const float* __restrict__ Wcls, const float* __restrict__ bcls,
    const float* __restrict__ ssum, const float* __restrict__ ssq,
    const float* __restrict__ gamma_p, const float* __restrict__ beta_p,
    float invN, float* __restrict__ out)
{
    __shared__ float s_pool[D];
    int g = blockIdx.x, tid = threadIdx.x;

    int lo = 0, hi = N;
    while (lo < hi) { int mid = (lo + hi) >> 1; if (batch[mid] < g) lo = mid + 1; else hi = mid; }
    int start = lo;
    hi = N;
    while (lo < hi) { int mid = (lo + hi) >> 1; if (batch[mid] < g + 1) lo = mid + 1; else hi = mid; }
    int end = lo;

    if (tid < D) s_pool[tid] = 0.f;
    __syncthreads();

    int col = tid & 63, rg = tid >> 6;
    float mean = ssum[col] * invN;
    float var = fmaf(-mean, mean, ssq[col] * invN);
    var = var < 0.f ? 0.f : var;
    float sc = gamma_p[col] * rsqrtf(var + BN_EPS);
    float sh_ = beta_p[col] - mean * sc;

    float p0 = 0.f, p1 = 0.f, p2 = 0.f, p3 = 0.f;
    int r = start + rg;
    for (; r + 48 < end; r += 64) {
        float a0 = __half2float(hfin[(size_t)(r     ) * D + col]);
        float a1 = __half2float(hfin[(size_t)(r + 16) * D + col]);
        float a2 = __half2float(hfin[(size_t)(r + 32) * D + col]);
        float a3 = __half2float(hfin[(size_t)(r + 48) * D + col]);
        p0 += fmaxf(fmaf(a0, sc, sh_), 0.f);
        p1 += fmaxf(fmaf(a1, sc, sh_), 0.f);
        p2 += fmaxf(fmaf(a2, sc, sh_), 0.f);
        p3 += fmaxf(fmaf(a3, sc, sh_), 0.f);
    }
    for (; r < end; r += 16)
        p0 += fmaxf(fmaf(__half2float(hfin[(size_t)r * D + col]), sc, sh_), 0.f);
    atomicAdd(&s_pool[col], ((p0 + p1) + (p2 + p3)));
    __syncthreads();

    float cnt = (float)(end - start);
    float denom = cnt > 1.f ? cnt : 1.f;
    if (tid < D) s_pool[tid] /= denom;
    __syncthreads();

    if (tid < 10) {
        float acc = bcls[tid];
#pragma unroll
        for (int d = 0; d < D; d++) acc = fmaf(s_pool[d], Wcls[d * 10 + tid], acc);
        out[g * 10 + tid] = acc;
    }
}

// ---------------- launch -----------------------------------------------------
extern "C" void kernel_launch(void* const* d_in, const int* in_sizes, int n_in,
                              void* d_out, int out_size)
{
    const float* x     = (const float*)d_in[0];
    const int*   ei    = (const int*)d_in[1];
    const int*   batch = (const int*)d_in[2];
    const float* Wrel  = (const float*)d_in[3];
    const float* brel  = (const float*)d_in[4];
    const float* Wroot = (const float*)d_in[5];
    const float* gamma = (const float*)d_in[6];
    const float* beta  = (const float*)d_in[7];
    const float* Wcls  = (const float*)d_in[8];
    const float* bcls  = (const float*)d_in[9];
    float* out = (float*)d_out;

    int N = in_sizes[0] / D;
    int E = in_sizes[1] / 2;
    int G = out_size / 10;
    int NB = (N + 1023) / 1024;
    float invN = 1.f / (float)N;
    int NTILES = (N + TILE - 1) / TILE;
    int total8 = N * 8;

    static int attr_done = 0;
    if (!attr_done) {
        cudaFuncSetAttribute(k_layer<0>, cudaFuncAttributeMaxDynamicSharedMemorySize, SMEM_BYTES);
        cudaFuncSetAttribute(k_layer<1>, cudaFuncAttributeMaxDynamicSharedMemorySize, SMEM_BYTES);
        attr_done = 1;
    }

    __half *xh, *hA, *hB;
    float *s0, *q0, *s1, *q1, *s2, *q2;
    cudaGetSymbolAddress((void**)&xh, g_xh);
    cudaGetSymbolAddress((void**)&hA, g_hA);
    cudaGetSymbolAddress((void**)&hB, g_hB);
    cudaGetSymbolAddress((void**)&s0, g_s0);
    cudaGetSymbolAddress((void**)&q0, g_q0);
    cudaGetSymbolAddress((void**)&s1, g_s1);
    cudaGetSymbolAddress((void**)&q1, g_q1);
    cudaGetSymbolAddress((void**)&s2, g_s2);
    cudaGetSymbolAddress((void**)&q2, g_q2);

    // K1: full CSR build + convert (internal grid barriers)
    k_csr<<<CSR_BLOCKS, 256>>>(x, ei, N, E, NB, total8);

    // K2-K4: fused gather+GEMM per layer
    k_layer<0><<<NTILES, 256, SMEM_BYTES>>>(xh, hA, Wrel, brel, Wroot,
                                            nullptr, nullptr, nullptr, nullptr,
                                            s0, q0, invN, N);
    k_layer<1><<<NTILES, 256, SMEM_BYTES>>>(hA, hB, Wrel + 4096, brel + 64, Wroot + 4096,
                                            s0, q0, gamma, beta,
                                            s1, q1, invN, N);
    k_layer<1><<<NTILES, 256, SMEM_BYTES>>>(hB, hA, Wrel + 8192, brel + 128, Wroot + 8192,
                                            s1, q1, gamma + 64, beta + 64,
                                            s2, q2, invN, N);

    // K5: pool (applies layer-2 BN+ReLU from s2/q2) + classifier
    k_pool<<<G, 1024>>>(hA, batch, N, Wcls, bcls,
                        s2, q2, gamma + 128, beta + 128, invN, out);
}

// round 12
// speedup vs baseline: 1.0995x; 1.0995x over previous
#include <cuda_runtime.h>
#include <cuda_fp16.h>

#define D 64
#define MAXN 100000
#define MAXE 1250000
#define BN_EPS 1e-5f
#define TILE 128
#define AROWH 136
#define WROWH 72

__device__ __forceinline__ __half2 u2h2(unsigned u) { return *reinterpret_cast<__half2*>(&u); }
__device__ __forceinline__ unsigned h2u(__half2 h) { return *reinterpret_cast<unsigned*>(&h); }

// ---------------- static device scratch -------------------------------------
__device__ int   g_deg[MAXN];          // zero at module load; re-zeroed by scan1 every run
__device__ int   g_rowptr[MAXN + 1];
__device__ int   g_cursor[MAXN + 1];
__device__ int   g_blocksums[256];
__device__ int   g_srcsorted[MAXE];
__device__ __align__(16) __half g_xh[(size_t)MAXN * D];
__device__ __align__(16) __half g_msg[(size_t)MAXN * D];
__device__ __align__(16) __half g_hA[(size_t)MAXN * D];
__device__ __align__(16) __half g_hB[(size_t)MAXN * D];
__device__ __align__(16) float g_s0[D];
__device__ __align__(16) float g_q0[D];
__device__ __align__(16) float g_s1[D];
__device__ __align__(16) float g_q1[D];
__device__ __align__(16) float g_s2[D];
__device__ __align__(16) float g_q2[D];
__device__ unsigned g_bar_cnt;   // monotonic, never reset

// ---------------- grid barrier (monotonic counter, wrap-safe) ----------------
__device__ __forceinline__ void grid_bar() {
    __syncthreads();
    if (threadIdx.x == 0) {
        __threadfence();
        unsigned t = atomicAdd(&g_bar_cnt, 1u);
        unsigned target = t - (t % gridDim.x) + gridDim.x;
        if ((t % gridDim.x) != gridDim.x - 1) {
            volatile unsigned* p = &g_bar_cnt;
            while ((int)(*p - target) < 0) __nanosleep(64);
        }
        __threadfence();
    }
    __syncthreads();
}

// ---------------- K_csr: convert + hist | scan1 | scan23 | bucket ------------
#define CSR_BLOCKS 392
__global__ void __launch_bounds__(256) k_csr(
    const float* __restrict__ x, const int* __restrict__ ei,
    int N, int E, int NB, int total8)
{
    __shared__ int ish[256];
    int tid = threadIdx.x;
    int gtid = blockIdx.x * 256 + tid;
    int gstride = gridDim.x * 256;

    // ---- phase A: convert x -> fp16, zero stats, histogram ----
    for (int i = gtid; i < total8; i += gstride) {
        float4 a = ((const float4*)x)[i * 2];
        float4 b = ((const float4*)x)[i * 2 + 1];
        uint4 o;
        o.x = h2u(__floats2half2_rn(a.x, a.y));
        o.y = h2u(__floats2half2_rn(a.z, a.w));
        o.z = h2u(__floats2half2_rn(b.x, b.y));
        o.w = h2u(__floats2half2_rn(b.z, b.w));
        ((uint4*)g_xh)[i] = o;
    }
    if (blockIdx.x == 0 && tid < D) {
        g_s0[tid] = 0.f; g_q0[tid] = 0.f;
        g_s1[tid] = 0.f; g_q1[tid] = 0.f;
        g_s2[tid] = 0.f; g_q2[tid] = 0.f;
    }
    for (int e = gtid; e < E; e += gstride)
        atomicAdd(&g_deg[ei[E + e]], 1);
    grid_bar();

    // ---- phase B: scan1 (read deg, RE-ZERO deg for next run, local scan) ----
    if (blockIdx.x < NB) {
        int base = blockIdx.x * 1024 + tid * 4;
        int v0 = 0, v1 = 0, v2 = 0, v3 = 0;
        if (base + 0 < N) { v0 = g_deg[base + 0]; g_deg[base + 0] = 0; }
        if (base + 1 < N) { v1 = g_deg[base + 1]; g_deg[base + 1] = 0; }
        if (base + 2 < N) { v2 = g_deg[base + 2]; g_deg[base + 2] = 0; }
        if (base + 3 < N) { v3 = g_deg[base + 3]; g_deg[base + 3] = 0; }
        int t0 = v0, t1 = t0 + v1, t2 = t1 + v2, t3 = t2 + v3;
        ish[tid] = t3;
        __syncthreads();
        for (int off = 1; off < 256; off <<= 1) {
            int a = (tid >= off) ? ish[tid - off] : 0;
            __syncthreads();
            ish[tid] += a;
            __syncthreads();
        }
        int excl = ish[tid] - t3;
        if (base + 0 < N) g_rowptr[base + 1] = excl + t0;
        if (base + 1 < N) g_rowptr[base + 2] = excl + t1;
        if (base + 2 < N) g_rowptr[base + 3] = excl + t2;
        if (base + 3 < N) g_rowptr[base + 4] = excl + t3;
        if (tid == 255) g_blocksums[blockIdx.x] = ish[255];
    }
    grid_bar();

    // ---- phase C: scan23 (rescan blocksums, apply offset, fill cursor) ----
    if (blockIdx.x < NB) {
        int v = (tid < NB) ? g_blocksums[tid] : 0;
        ish[tid] = v;
        __syncthreads();
        for (int off = 1; off < 256; off <<= 1) {
            int a = (tid >= off) ? ish[tid - off] : 0;
            __syncthreads();
            ish[tid] += a;
            __syncthreads();
        }
        int off = (blockIdx.x == 0) ? 0 : ish[blockIdx.x - 1];
        int base = blockIdx.x * 1024 + tid * 4;
#pragma unroll
        for (int i = 0; i < 4; i++) {
            int idx = base + i;
            if (idx < N) {
                int val = g_rowptr[idx + 1] + off;
                g_rowptr[idx + 1] = val;
                if (idx + 1 < N) g_cursor[idx + 1] = val;
            }
        }
        if (blockIdx.x == 0 && tid == 0) { g_rowptr[0] = 0; g_cursor[0] = 0; }
    }
    grid_bar();

    // ---- phase D: bucket ----
    for (int e = gtid; e < E; e += gstride) {
        int d = ei[E + e];
        int pos = atomicAdd(&g_cursor[d], 1);
        g_srcsorted[pos] = ei[e];
    }
}

// ---------------- gather: warp per node, fp16 in/out --------------------------
template<int TF>
__global__ void __launch_bounds__(256) k_gather(
    const __half* __restrict__ x_src,
    const float* __restrict__ ssum, const float* __restrict__ ssq,
    const float* __restrict__ gamma_p, const float* __restrict__ beta_p,
    float invN, int N)
{
    int lane = threadIdx.x & 31;
    int node = (blockIdx.x * blockDim.x + threadIdx.x) >> 5;
    if (node >= N) return;
    int q = lane >> 3;
    int c8 = lane & 7;

    __half2 sc2[4], sh2[4];
    if (TF) {
#pragma unroll
        for (int j = 0; j < 4; j++) {
            float scf[2], shf[2];
#pragma unroll
            for (int c = 0; c < 2; c++) {
                int col = c8 * 8 + j * 2 + c;
                float mean = ssum[col] * invN;
                float var = fmaf(-mean, mean, ssq[col] * invN);
                var = var < 0.f ? 0.f : var;
                float s = gamma_p[col] * rsqrtf(var + BN_EPS);
                scf[c] = s;
                shf[c] = beta_p[col] - mean * s;
            }
            sc2[j] = __floats2half2_rn(scf[0], scf[1]);
            sh2[j] = __floats2half2_rn(shf[0], shf[1]);
        }
    }

    float acc[8];
#pragma unroll
    for (int j = 0; j < 8; j++) acc[j] = 0.f;

    int rs = g_rowptr[node], re = g_rowptr[node + 1];
    for (int base = rs; base < re; base += 32) {
        int jj = base + lane;
        int sj = (jj < re) ? g_srcsorted[jj] : 0;
        int cnt = min(32, re - base);
        for (int u = 0; u < cnt; u += 4) {
            int i0 = u + q;
            int s = __shfl_sync(0xffffffffu, sj, i0 & 31);
            if (i0 < cnt) {
                uint4 raw = *(const uint4*)(x_src + (size_t)s * D + c8 * 8);
                __half2 v0 = u2h2(raw.x), v1 = u2h2(raw.y), v2 = u2h2(raw.z), v3 = u2h2(raw.w);
                if (TF) {
                    __half2 z = __float2half2_rn(0.f);
                    v0 = __hmax2(__hfma2(v0, sc2[0], sh2[0]), z);
                    v1 = __hmax2(__hfma2(v1, sc2[1], sh2[1]), z);
                    v2 = __hmax2(__hfma2(v2, sc2[2], sh2[2]), z);
                    v3 = __hmax2(__hfma2(v3, sc2[3], sh2[3]), z);
                }
                float2 f0 = __half22float2(v0), f1 = __half22float2(v1);
                float2 f2 = __half22float2(v2), f3 = __half22float2(v3);
                acc[0] += f0.x; acc[1] += f0.y; acc[2] += f1.x; acc[3] += f1.y;
                acc[4] += f2.x; acc[5] += f2.y; acc[6] += f3.x; acc[7] += f3.y;
            }
        }
    }

#pragma unroll
    for (int off = 8; off <= 16; off <<= 1)
#pragma unroll
        for (int j = 0; j < 8; j++) acc[j] += __shfl_xor_sync(0xffffffffu, acc[j], off);

    if (lane < 8) {
        uint4 o;
        o.x = h2u(__floats2half2_rn(acc[0], acc[1]));
        o.y = h2u(__floats2half2_rn(acc[2], acc[3]));
        o.z = h2u(__floats2half2_rn(acc[4], acc[5]));
        o.w = h2u(__floats2half2_rn(acc[6], acc[7]));
        *(uint4*)(g_msg + (size_t)node * D + lane * 8) = o;
    }
}

// ---------------- tensor-core GEMM: [msg|x](Nx128) @ [Wrel;Wroot](128x64) -----
#define SMEM_A_BYTES (128 * AROWH * 2)
#define SMEM_W_OFF   SMEM_A_BYTES
#define SMEM_F_OFF   (SMEM_A_BYTES + 128 * WROWH * 2)
#define SMEM_BYTES   (SMEM_F_OFF + 64 * 4 * 3 + 64 * 2 * 2)

template<int TF>
__global__ void __launch_bounds__(256) k_gemm(
    const __half* __restrict__ x_src, __half* __restrict__ h_out,
    const float* __restrict__ Wrel, const float* __restrict__ brel,
    const float* __restrict__ Wroot,
    const float* __restrict__ ssum_in, const float* __restrict__ ssq_in,
    const float* __restrict__ gamma_p, const float* __restrict__ beta_p,
    float* __restrict__ ssum_out, float* __restrict__ ssq_out,
    float invN, int N)
{
    extern __shared__ char smemc[];
    __half* a_sh = (__half*)smemc;
    __half* w_sh = (__half*)(smemc + SMEM_W_OFF);
    float* s_bias = (float*)(smemc + SMEM_F_OFF);
    float* s_sum = s_bias + 64;
    float* s_sq  = s_sum + 64;
    __half* s_sch = (__half*)(s_sq + 64);
    __half* s_shh = s_sch + 64;

    int tid = threadIdx.x;
    int lane = tid & 31;
    int w = tid >> 5;

    // stage W (fp32 -> fp16) once per block
    for (int i = tid; i < 1024; i += 256) {
        int k = i >> 4, n4 = (i & 15) * 4;
        float4 v = ((const float4*)Wrel)[i];
        uint2 hv;
        hv.x = h2u(__floats2half2_rn(v.x, v.y));
        hv.y = h2u(__floats2half2_rn(v.z, v.w));
        *(uint2*)(w_sh + k * WROWH + n4) = hv;
        float4 u = ((const float4*)Wroot)[i];
        uint2 hu;
        hu.x = h2u(__floats2half2_rn(u.x, u.y));
        hu.y = h2u(__floats2half2_rn(u.z, u.w));
        *(uint2*)(w_sh + (64 + k) * WROWH + n4) = hu;
    }
    if (tid < 64) {
        s_bias[tid] = brel[tid];
        s_sum[tid] = 0.f;
        s_sq[tid] = 0.f;
        if (TF) {
            float mean = ssum_in[tid] * invN;
            float var = fmaf(-mean, mean, ssq_in[tid] * invN);
            var = var < 0.f ? 0.f : var;
            float s = gamma_p[tid] * rsqrtf(var + BN_EPS);
            s_sch[tid] = __float2half_rn(s);
            s_shh[tid] = __float2half_rn(beta_p[tid] - mean * s);
        }
    }

    unsigned sbase = (unsigned)__cvta_generic_to_shared(smemc);
    unsigned a_addr = sbase + ((16 * w + (lane & 15)) * AROWH + ((lane >> 4) << 3)) * 2;
    unsigned b_addr = sbase + SMEM_W_OFF + ((lane & 15) * WROWH + ((lane >> 4) << 3)) * 2;

    int grp = lane >> 2, tig = lane & 3;
    float sl[16], ql[16];
#pragma unroll
    for (int i = 0; i < 16; i++) { sl[i] = 0.f; ql[i] = 0.f; }

    int ntiles = (N + TILE - 1) / TILE;
    for (int tile = blockIdx.x; tile < ntiles; tile += gridDim.x) {
        int tile0 = tile * TILE;
        __syncthreads();

        // stage A = [msg | x] rows (fp16): 128 rows x 16 uint4 (128 halves/row)
        for (int i = tid; i < 2048; i += 256) {
            int r = i >> 4, seg = i & 15;
            int node = tile0 + r;
            uint4 val = make_uint4(0u, 0u, 0u, 0u);
            if (node < N) {
                if (seg < 8) {
                    val = ((const uint4*)(g_msg + (size_t)node * D))[seg];
                } else {
                    val = ((const uint4*)(x_src + (size_t)node * D))[seg - 8];
                    if (TF) {
                        int cb2 = (seg - 8) * 4;
                        const __half2* scp = (const __half2*)s_sch;
                        const __half2* shp = (const __half2*)s_shh;
                        __half2 z = __float2half2_rn(0.f);
                        val.x = h2u(__hmax2(__hfma2(u2h2(val.x), scp[cb2 + 0], shp[cb2 + 0]), z));
                        val.y = h2u(__hmax2(__hfma2(u2h2(val.y), scp[cb2 + 1], shp[cb2 + 1]), z));
                        val.z = h2u(__hmax2(__hfma2(u2h2(val.z), scp[cb2 + 2], shp[cb2 + 2]), z));
                        val.w = h2u(__hmax2(__hfma2(u2h2(val.w), scp[cb2 + 3], shp[cb2 + 3]), z));
                    }
                }
            }
            *(uint4*)(a_sh + r * AROWH + seg * 8) = val;
        }
        __syncthreads();

        // accumulators (init with bias)
        float c[8][4];
#pragma unroll
        for (int nt = 0; nt < 8; nt++) {
            float b0 = s_bias[nt * 8 + tig * 2];
            float b1 = s_bias[nt * 8 + tig * 2 + 1];
            c[nt][0] = b0; c[nt][1] = b1; c[nt][2] = b0; c[nt][3] = b1;
        }

#pragma unroll
        for (int ks = 0; ks < 8; ks++) {
            unsigned a0, a1, a2, a3;
            asm volatile("ldmatrix.sync.aligned.m8n8.x4.shared.b16 {%0,%1,%2,%3}, [%4];"
                         : "=r"(a0), "=r"(a1), "=r"(a2), "=r"(a3)
                         : "r"(a_addr + ks * 32));
#pragma unroll
            for (int nt4 = 0; nt4 < 4; nt4++) {
                unsigned b0, b1, b2, b3;
                asm volatile("ldmatrix.sync.aligned.m8n8.x4.trans.shared.b16 {%0,%1,%2,%3}, [%4];"
                             : "=r"(b0), "=r"(b1), "=r"(b2), "=r"(b3)
                             : "r"(b_addr + ks * (16 * WROWH * 2) + nt4 * 32));
                asm volatile("mma.sync.aligned.m16n8k16.row.col.f32.f16.f16.f32 "
                             "{%0,%1,%2,%3}, {%4,%5,%6,%7}, {%8,%9}, {%0,%1,%2,%3};"
                             : "+f"(c[2 * nt4][0]), "+f"(c[2 * nt4][1]), "+f"(c[2 * nt4][2]), "+f"(c[2 * nt4][3])
                             : "r"(a0), "r"(a1), "r"(a2), "r"(a3), "r"(b0), "r"(b1));
                asm volatile("mma.sync.aligned.m16n8k16.row.col.f32.f16.f16.f32 "
                             "{%0,%1,%2,%3}, {%4,%5,%6,%7}, {%8,%9}, {%0,%1,%2,%3};"
                             : "+f"(c[2 * nt4 + 1][0]), "+f"(c[2 * nt4 + 1][1]), "+f"(c[2 * nt4 + 1][2]), "+f"(c[2 * nt4 + 1][3])
                             : "r"(a0), "r"(a1), "r"(a2), "r"(a3), "r"(b2), "r"(b3));
            }
        }

        // epilogue: store h (fp16) + accumulate BN stats
        int row0 = tile0 + 16 * w + grp;
        int row1 = row0 + 8;
        bool v0 = row0 < N, v1 = row1 < N;
#pragma unroll
        for (int nt = 0; nt < 8; nt++) {
            int col = nt * 8 + tig * 2;
            if (v0) {
                *(unsigned*)(h_out + (size_t)row0 * D + col) = h2u(__floats2half2_rn(c[nt][0], c[nt][1]));
                sl[2 * nt]     += c[nt][0];
                ql[2 * nt]      = fmaf(c[nt][0], c[nt][0], ql[2 * nt]);
                sl[2 * nt + 1] += c[nt][1];
                ql[2 * nt + 1]  = fmaf(c[nt][1], c[nt][1], ql[2 * nt + 1]);
            }
            if (v1) {
                *(unsigned*)(h_out + (size_t)row1 * D + col) = h2u(__floats2half2_rn(c[nt][2], c[nt][3]));
                sl[2 * nt]     += c[nt][2];
                ql[2 * nt]      = fmaf(c[nt][2], c[nt][2], ql[2 * nt]);
                sl[2 * nt + 1] += c[nt][3];
                ql[2 * nt + 1]  = fmaf(c[nt][3], c[nt][3], ql[2 * nt + 1]);
            }
        }
    }

    // reduce stats over row-groups
#pragma unroll
    for (int off = 4; off <= 16; off <<= 1) {
#pragma unroll
        for (int i = 0; i < 16; i++) {
            sl[i] += __shfl_xor_sync(0xffffffffu, sl[i], off);
            ql[i] += __shfl_xor_sync(0xffffffffu, ql[i], off);
        }
    }
    if (lane < 4) {
#pragma unroll
        for (int nt = 0; nt < 8; nt++) {
            atomicAdd(&s_sum[nt * 8 + 2 * lane],     sl[2 * nt]);
            atomicAdd(&s_sum[nt * 8 + 2 * lane + 1], sl[2 * nt + 1]);
            atomicAdd(&s_sq[nt * 8 + 2 * lane],      ql[2 * nt]);
            atomicAdd(&s_sq[nt * 8 + 2 * lane + 1],  ql[2 * nt + 1]);
        }
    }
    __syncthreads();
    if (tid < 64) atomicAdd(&ssum_out[tid], s_sum[tid]);
    else if (tid < 128) atomicAdd(&ssq_out[tid - 64], s_sq[tid - 64]);
}

// ---------------- pooling + classifier (final BN+ReLU inline) ----------------
__global__ void __launch_bounds__(1024) k_pool(
    const __half* __restrict__ hfin, const int* __restrict__ batch, int N,
    const float* __restrict__ Wcls, const float* __restrict__ bcls,
    const float* __restrict__ ssum, const float* __restrict__ ssq,
    const float* __restrict__ gamma_p, const float* __restrict__ beta_p,
    float invN, float* __restrict__ out)
{
    __shared__ float s_pool[D];
    int g = blockIdx.x, tid = threadIdx.x;

    int lo = 0, hi = N;
    while (lo < hi) { int mid = (lo + hi) >> 1; if (batch[mid] < g) lo = mid + 1; else hi = mid; }
    int start = lo;
    hi = N;
    while (lo < hi) { int mid = (lo + hi) >> 1; if (batch[mid] < g + 1) lo = mid + 1; else hi = mid; }
    int end = lo;

    if (tid < D) s_pool[tid] = 0.f;
    __syncthreads();

    int col = tid & 63, rg = tid >> 6;
    float mean = ssum[col] * invN;
    float var = fmaf(-mean, mean, ssq[col] * invN);
    var = var < 0.f ? 0.f : var;
    float sc = gamma_p[col] * rsqrtf(var + BN_EPS);
    float sh_ = beta_p[col] - mean * sc;

    float p0 = 0.f, p1 = 0.f, p2 = 0.f, p3 = 0.f;
    int r = start + rg;
    for (; r + 48 < end; r += 64) {
        float a0 = __half2float(hfin[(size_t)(r     ) * D + col]);
        float a1 = __half2float(hfin[(size_t)(r + 16) * D + col]);
        float a2 = __half2float(hfin[(size_t)(r + 32) * D + col]);
        float a3 = __half2float(hfin[(size_t)(r + 48) * D + col]);
        p0 += fmaxf(fmaf(a0, sc, sh_), 0.f);
        p1 += fmaxf(fmaf(a1, sc, sh_), 0.f);
        p2 += fmaxf(fmaf(a2, sc, sh_), 0.f);
        p3 += fmaxf(fmaf(a3, sc, sh_), 0.f);
    }
    for (; r < end; r += 16)
        p0 += fmaxf(fmaf(__half2float(hfin[(size_t)r * D + col]), sc, sh_), 0.f);
    atomicAdd(&s_pool[col], ((p0 + p1) + (p2 + p3)));
    __syncthreads();

    float cnt = (float)(end - start);
    float denom = cnt > 1.f ? cnt : 1.f;
    if (tid < D) s_pool[tid] /= denom;
    __syncthreads();

    if (tid < 10) {
        float acc = bcls[tid];
#pragma unroll
        for (int d = 0; d < D; d++) acc = fmaf(s_pool[d], Wcls[d * 10 + tid], acc);
        out[g * 10 + tid] = acc;
    }
}

// ---------------- launch -----------------------------------------------------
extern "C" void kernel_launch(void* const* d_in, const int* in_sizes, int n_in,
                              void* d_out, int out_size)
{
    const float* x     = (const float*)d_in[0];
    const int*   ei    = (const int*)d_in[1];
    const int*   batch = (const int*)d_in[2];
    const float* Wrel  = (const float*)d_in[3];
    const float* brel  = (const float*)d_in[4];
    const float* Wroot = (const float*)d_in[5];
    const float* gamma = (const float*)d_in[6];
    const float* beta  = (const float*)d_in[7];
    const float* Wcls  = (const float*)d_in[8];
    const float* bcls  = (const float*)d_in[9];
    float* out = (float*)d_out;

    int N = in_sizes[0] / D;
    int E = in_sizes[1] / 2;
    int G = out_size / 10;
    int NB = (N + 1023) / 1024;
    float invN = 1.f / (float)N;
    int NTILES = (N + TILE - 1) / TILE;
    int GATHER_BLOCKS = (N * 32 + 255) / 256;
    int total8 = N * 8;
    int GEMM_BLOCKS = NTILES < 296 ? NTILES : 296;

    static int attr_done = 0;
    if (!attr_done) {
        cudaFuncSetAttribute(k_gemm<0>, cudaFuncAttributeMaxDynamicSharedMemorySize, SMEM_BYTES);
        cudaFuncSetAttribute(k_gemm<1>, cudaFuncAttributeMaxDynamicSharedMemorySize, SMEM_BYTES);
        attr_done = 1;
    }

    __half *xh, *hA, *hB;
    float *s0, *q0, *s1, *q1, *s2, *q2;
    cudaGetSymbolAddress((void**)&xh, g_xh);
    cudaGetSymbolAddress((void**)&hA, g_hA);
    cudaGetSymbolAddress((void**)&hB, g_hB);
    cudaGetSymbolAddress((void**)&s0, g_s0);
    cudaGetSymbolAddress((void**)&q0, g_q0);
    cudaGetSymbolAddress((void**)&s1, g_s1);
    cudaGetSymbolAddress((void**)&q1, g_q1);
    cudaGetSymbolAddress((void**)&s2, g_s2);
    cudaGetSymbolAddress((void**)&q2, g_q2);

    // K1: full CSR build + convert (internal grid barriers)
    k_csr<<<CSR_BLOCKS, 256>>>(x, ei, N, E, NB, total8);

    // layer 0: xh -> hA (stats -> s0/q0)
    k_gather<0><<<GATHER_BLOCKS, 256>>>(xh, nullptr, nullptr, nullptr, nullptr, invN, N);
    k_gemm<0><<<GEMM_BLOCKS, 256, SMEM_BYTES>>>(xh, hA, Wrel, brel, Wroot,
                                                nullptr, nullptr, nullptr, nullptr,
                                                s0, q0, invN, N);

    // layer 1: hA -> hB (BN from s0; stats -> s1)
    k_gather<1><<<GATHER_BLOCKS, 256>>>(hA, s0, q0, gamma, beta, invN, N);
    k_gemm<1><<<GEMM_BLOCKS, 256, SMEM_BYTES>>>(hA, hB, Wrel + 4096, brel + 64, Wroot + 4096,
                                                s0, q0, gamma, beta,
                                                s1, q1, invN, N);

    // layer 2: hB -> hA (BN from s1; stats -> s2)
    k_gather<1><<<GATHER_BLOCKS, 256>>>(hB, s1, q1, gamma + 64, beta + 64, invN, N);
    k_gemm<1><<<GEMM_BLOCKS, 256, SMEM_BYTES>>>(hB, hA, Wrel + 8192, brel + 128, Wroot + 8192,
                                                s1, q1, gamma + 64, beta + 64,
                                                s2, q2, invN, N);

    // pool (applies layer-2 BN+ReLU from s2/q2) + classifier
    k_pool<<<G, 1024>>>(hA, batch, N, Wcls, bcls,
                        s2, q2, gamma + 128, beta + 128, invN, out);
}

// round 13
// speedup vs baseline: 1.1187x; 1.0175x over previous
#include <cuda_runtime.h>
#include <cuda_fp16.h>

#define D 64
#define MAXN 100000
#define MAXE 1250000
#define BN_EPS 1e-5f
#define TILE 128
#define AROWH 136
#define WROWH 72

__device__ __forceinline__ __half2 u2h2(unsigned u) { return *reinterpret_cast<__half2*>(&u); }
__device__ __forceinline__ unsigned h2u(__half2 h) { return *reinterpret_cast<unsigned*>(&h); }

// ---------------- static device scratch -------------------------------------
__device__ int   g_deg[MAXN];          // zero at module load; re-zeroed by scan1 every run
__device__ int   g_rowptr[MAXN + 1];
__device__ int   g_cursor[MAXN + 1];
__device__ int   g_blocksums[256];
__device__ int   g_srcsorted[MAXE];
__device__ __align__(16) __half g_xh[(size_t)MAXN * D];
__device__ __align__(16) __half g_msg[(size_t)MAXN * D];
__device__ __align__(16) __half g_hA[(size_t)MAXN * D];
__device__ __align__(16) __half g_hB[(size_t)MAXN * D];
__device__ __align__(16) float g_s0[D];
__device__ __align__(16) float g_q0[D];
__device__ __align__(16) float g_s1[D];
__device__ __align__(16) float g_q1[D];
__device__ __align__(16) float g_s2[D];
__device__ __align__(16) float g_q2[D];
__device__ unsigned g_bar_cnt;   // monotonic, never reset

// ---------------- grid barrier (monotonic counter, wrap-safe) ----------------
__device__ __forceinline__ void grid_bar() {
    __syncthreads();
    if (threadIdx.x == 0) {
        __threadfence();
        unsigned t = atomicAdd(&g_bar_cnt, 1u);
        unsigned target = t - (t % gridDim.x) + gridDim.x;
        if ((t % gridDim.x) != gridDim.x - 1) {
            volatile unsigned* p = &g_bar_cnt;
            while ((int)(*p - target) < 0) __nanosleep(64);
        }
        __threadfence();
    }
    __syncthreads();
}

// ---------------- K_csr: convert + hist | scan1 | scan23 | bucket ------------
#define CSR_BLOCKS 392
__global__ void __launch_bounds__(256) k_csr(
    const float* __restrict__ x, const int* __restrict__ ei,
    int N, int E, int NB, int total8)
{
    __shared__ int ish[256];
    int tid = threadIdx.x;
    int gtid = blockIdx.x * 256 + tid;
    int gstride = gridDim.x * 256;

    // ---- phase A: convert x -> fp16, zero stats, histogram ----
    for (int i = gtid; i < total8; i += gstride) {
        float4 a = ((const float4*)x)[i * 2];
        float4 b = ((const float4*)x)[i * 2 + 1];
        uint4 o;
        o.x = h2u(__floats2half2_rn(a.x, a.y));
        o.y = h2u(__floats2half2_rn(a.z, a.w));
        o.z = h2u(__floats2half2_rn(b.x, b.y));
        o.w = h2u(__floats2half2_rn(b.z, b.w));
        ((uint4*)g_xh)[i] = o;
    }
    if (blockIdx.x == 0 && tid < D) {
        g_s0[tid] = 0.f; g_q0[tid] = 0.f;
        g_s1[tid] = 0.f; g_q1[tid] = 0.f;
        g_s2[tid] = 0.f; g_q2[tid] = 0.f;
    }
    for (int e = gtid; e < E; e += gstride)
        atomicAdd(&g_deg[ei[E + e]], 1);
    grid_bar();

    // ---- phase B: scan1 (read deg, RE-ZERO deg for next run, local scan) ----
    if (blockIdx.x < NB) {
        int base = blockIdx.x * 1024 + tid * 4;
        int v0 = 0, v1 = 0, v2 = 0, v3 = 0;
        if (base + 0 < N) { v0 = g_deg[base + 0]; g_deg[base + 0] = 0; }
        if (base + 1 < N) { v1 = g_deg[base + 1]; g_deg[base + 1] = 0; }
        if (base + 2 < N) { v2 = g_deg[base + 2]; g_deg[base + 2] = 0; }
        if (base + 3 < N) { v3 = g_deg[base + 3]; g_deg[base + 3] = 0; }
        int t0 = v0, t1 = t0 + v1, t2 = t1 + v2, t3 = t2 + v3;
        ish[tid] = t3;
        __syncthreads();
        for (int off = 1; off < 256; off <<= 1) {
            int a = (tid >= off) ? ish[tid - off] : 0;
            __syncthreads();
            ish[tid] += a;
            __syncthreads();
        }
        int excl = ish[tid] - t3;
        if (base + 0 < N) g_rowptr[base + 1] = excl + t0;
        if (base + 1 < N) g_rowptr[base + 2] = excl + t1;
        if (base + 2 < N) g_rowptr[base + 3] = excl + t2;
        if (base + 3 < N) g_rowptr[base + 4] = excl + t3;
        if (tid == 255) g_blocksums[blockIdx.x] = ish[255];
    }
    grid_bar();

    // ---- phase C: scan23 (rescan blocksums, apply offset, fill cursor) ----
    if (blockIdx.x < NB) {
        int v = (tid < NB) ? g_blocksums[tid] : 0;
        ish[tid] = v;
        __syncthreads();
        for (int off = 1; off < 256; off <<= 1) {
            int a = (tid >= off) ? ish[tid - off] : 0;
            __syncthreads();
            ish[tid] += a;
            __syncthreads();
        }
        int off = (blockIdx.x == 0) ? 0 : ish[blockIdx.x - 1];
        int base = blockIdx.x * 1024 + tid * 4;
#pragma unroll
        for (int i = 0; i < 4; i++) {
            int idx = base + i;
            if (idx < N) {
                int val = g_rowptr[idx + 1] + off;
                g_rowptr[idx + 1] = val;
                if (idx + 1 < N) g_cursor[idx + 1] = val;
            }
        }
        if (blockIdx.x == 0 && tid == 0) { g_rowptr[0] = 0; g_cursor[0] = 0; }
    }
    grid_bar();

    // ---- phase D: bucket ----
    for (int e = gtid; e < E; e += gstride) {
        int d = ei[E + e];
        int pos = atomicAdd(&g_cursor[d], 1);
        g_srcsorted[pos] = ei[e];
    }
}

// ---------------- gather: warp per node, fp16 chunk accumulation -------------
template<int TF>
__global__ void __launch_bounds__(256) k_gather(
    const __half* __restrict__ x_src,
    const float* __restrict__ ssum, const float* __restrict__ ssq,
    const float* __restrict__ gamma_p, const float* __restrict__ beta_p,
    float invN, int N)
{
    int lane = threadIdx.x & 31;
    int node = (blockIdx.x * blockDim.x + threadIdx.x) >> 5;
    if (node >= N) return;
    int q = lane >> 3;
    int c8 = lane & 7;

    __half2 sc2[4], sh2[4];
    if (TF) {
#pragma unroll
        for (int j = 0; j < 4; j++) {
            float scf[2], shf[2];
#pragma unroll
            for (int c = 0; c < 2; c++) {
                int col = c8 * 8 + j * 2 + c;
                float mean = ssum[col] * invN;
                float var = fmaf(-mean, mean, ssq[col] * invN);
                var = var < 0.f ? 0.f : var;
                float s = gamma_p[col] * rsqrtf(var + BN_EPS);
                scf[c] = s;
                shf[c] = beta_p[col] - mean * s;
            }
            sc2[j] = __floats2half2_rn(scf[0], scf[1]);
            sh2[j] = __floats2half2_rn(shf[0], shf[1]);
        }
    }

    float acc[8];
#pragma unroll
    for (int j = 0; j < 8; j++) acc[j] = 0.f;

    const __half2 z2 = __float2half2_rn(0.f);
    int rs = g_rowptr[node], re = g_rowptr[node + 1];
    for (int base = rs; base < re; base += 32) {
        int jj = base + lane;
        int sj = (jj < re) ? g_srcsorted[jj] : 0;
        int cnt = min(32, re - base);

        // fp16 chunk accumulators (<=8 adds each per chunk -> safe)
        __half2 h0 = z2, h1 = z2, h2 = z2, h3 = z2;
        for (int u = 0; u < cnt; u += 4) {
            int i0 = u + q;
            int s = __shfl_sync(0xffffffffu, sj, i0 & 31);
            if (i0 < cnt) {
                uint4 raw = *(const uint4*)(x_src + (size_t)s * D + c8 * 8);
                __half2 v0 = u2h2(raw.x), v1 = u2h2(raw.y), v2 = u2h2(raw.z), v3 = u2h2(raw.w);
                if (TF) {
                    v0 = __hmax2(__hfma2(v0, sc2[0], sh2[0]), z2);
                    v1 = __hmax2(__hfma2(v1, sc2[1], sh2[1]), z2);
                    v2 = __hmax2(__hfma2(v2, sc2[2], sh2[2]), z2);
                    v3 = __hmax2(__hfma2(v3, sc2[3], sh2[3]), z2);
                }
                h0 = __hadd2(h0, v0);
                h1 = __hadd2(h1, v1);
                h2 = __hadd2(h2, v2);
                h3 = __hadd2(h3, v3);
            }
        }
        // flush chunk to fp32
        float2 f0 = __half22float2(h0), f1 = __half22float2(h1);
        float2 f2 = __half22float2(h2), f3 = __half22float2(h3);
        acc[0] += f0.x; acc[1] += f0.y; acc[2] += f1.x; acc[3] += f1.y;
        acc[4] += f2.x; acc[5] += f2.y; acc[6] += f3.x; acc[7] += f3.y;
    }

#pragma unroll
    for (int off = 8; off <= 16; off <<= 1)
#pragma unroll
        for (int j = 0; j < 8; j++) acc[j] += __shfl_xor_sync(0xffffffffu, acc[j], off);

    if (lane < 8) {
        uint4 o;
        o.x = h2u(__floats2half2_rn(acc[0], acc[1]));
        o.y = h2u(__floats2half2_rn(acc[2], acc[3]));
        o.z = h2u(__floats2half2_rn(acc[4], acc[5]));
        o.w = h2u(__floats2half2_rn(acc[6], acc[7]));
        *(uint4*)(g_msg + (size_t)node * D + lane * 8) = o;
    }
}

// ---------------- tensor-core GEMM: [msg|x](Nx128) @ [Wrel;Wroot](128x64) -----
#define SMEM_A_BYTES (128 * AROWH * 2)
#define SMEM_W_OFF   SMEM_A_BYTES
#define SMEM_F_OFF   (SMEM_A_BYTES + 128 * WROWH * 2)
#define SMEM_BYTES   (SMEM_F_OFF + 64 * 4 * 3 + 64 * 2 * 2)

template<int TF>
__global__ void __launch_bounds__(256) k_gemm(
    const __half* __restrict__ x_src, __half* __restrict__ h_out,
    const float* __restrict__ Wrel, const float* __restrict__ brel,
    const float* __restrict__ Wroot,
    const float* __restrict__ ssum_in, const float* __restrict__ ssq_in,
    const float* __restrict__ gamma_p, const float* __restrict__ beta_p,
    float* __restrict__ ssum_out, float* __restrict__ ssq_out,
    float invN, int N)
{
    extern __shared__ char smemc[];
    __half* a_sh = (__half*)smemc;
    __half* w_sh = (__half*)(smemc + SMEM_W_OFF);
    float* s_bias = (float*)(smemc + SMEM_F_OFF);
    float* s_sum = s_bias + 64;
    float* s_sq  = s_sum + 64;
    __half* s_sch = (__half*)(s_sq + 64);
    __half* s_shh = s_sch + 64;

    int tid = threadIdx.x;
    int lane = tid & 31;
    int w = tid >> 5;

    // stage W (fp32 -> fp16) once per block
    for (int i = tid; i < 1024; i += 256) {
        int k = i >> 4, n4 = (i & 15) * 4;
        float4 v = ((const float4*)Wrel)[i];
        uint2 hv;
        hv.x = h2u(__floats2half2_rn(v.x, v.y));
        hv.y = h2u(__floats2half2_rn(v.z, v.w));
        *(uint2*)(w_sh + k * WROWH + n4) = hv;
        float4 u = ((const float4*)Wroot)[i];
        uint2 hu;
        hu.x = h2u(__floats2half2_rn(u.x, u.y));
        hu.y = h2u(__floats2half2_rn(u.z, u.w));
        *(uint2*)(w_sh + (64 + k) * WROWH + n4) = hu;
    }
    if (tid < 64) {
        s_bias[tid] = brel[tid];
        s_sum[tid] = 0.f;
        s_sq[tid] = 0.f;
        if (TF) {
            float mean = ssum_in[tid] * invN;
            float var = fmaf(-mean, mean, ssq_in[tid] * invN);
            var = var < 0.f ? 0.f : var;
            float s = gamma_p[tid] * rsqrtf(var + BN_EPS);
            s_sch[tid] = __float2half_rn(s);
            s_shh[tid] = __float2half_rn(beta_p[tid] - mean * s);
        }
    }

    unsigned sbase = (unsigned)__cvta_generic_to_shared(smemc);
    unsigned a_addr = sbase + ((16 * w + (lane & 15)) * AROWH + ((lane >> 4) << 3)) * 2;
    unsigned b_addr = sbase + SMEM_W_OFF + ((lane & 15) * WROWH + ((lane >> 4) << 3)) * 2;

    int grp = lane >> 2, tig = lane & 3;
    float sl[16], ql[16];
#pragma unroll
    for (int i = 0; i < 16; i++) { sl[i] = 0.f; ql[i] = 0.f; }

    int ntiles = (N + TILE - 1) / TILE;
    for (int tile = blockIdx.x; tile < ntiles; tile += gridDim.x) {
        int tile0 = tile * TILE;
        __syncthreads();

        // stage A = [msg | x] rows (fp16): 128 rows x 16 uint4 (128 halves/row)
        for (int i = tid; i < 2048; i += 256) {
            int r = i >> 4, seg = i & 15;
            int node = tile0 + r;
            uint4 val = make_uint4(0u, 0u, 0u, 0u);
            if (node < N) {
                if (seg < 8) {
                    val = ((const uint4*)(g_msg + (size_t)node * D))[seg];
                } else {
                    val = ((const uint4*)(x_src + (size_t)node * D))[seg - 8];
                    if (TF) {
                        int cb2 = (seg - 8) * 4;
                        const __half2* scp = (const __half2*)s_sch;
                        const __half2* shp = (const __half2*)s_shh;
                        __half2 z = __float2half2_rn(0.f);
                        val.x = h2u(__hmax2(__hfma2(u2h2(val.x), scp[cb2 + 0], shp[cb2 + 0]), z));
                        val.y = h2u(__hmax2(__hfma2(u2h2(val.y), scp[cb2 + 1], shp[cb2 + 1]), z));
                        val.z = h2u(__hmax2(__hfma2(u2h2(val.z), scp[cb2 + 2], shp[cb2 + 2]), z));
                        val.w = h2u(__hmax2(__hfma2(u2h2(val.w), scp[cb2 + 3], shp[cb2 + 3]), z));
                    }
                }
            }
            *(uint4*)(a_sh + r * AROWH + seg * 8) = val;
        }
        __syncthreads();

        // accumulators (init with bias)
        float c[8][4];
#pragma unroll
        for (int nt = 0; nt < 8; nt++) {
            float b0 = s_bias[nt * 8 + tig * 2];
            float b1 = s_bias[nt * 8 + tig * 2 + 1];
            c[nt][0] = b0; c[nt][1] = b1; c[nt][2] = b0; c[nt][3] = b1;
        }

#pragma unroll
        for (int ks = 0; ks < 8; ks++) {
            unsigned a0, a1, a2, a3;
            asm volatile("ldmatrix.sync.aligned.m8n8.x4.shared.b16 {%0,%1,%2,%3}, [%4];"
                         : "=r"(a0), "=r"(a1), "=r"(a2), "=r"(a3)
                         : "r"(a_addr + ks * 32));
#pragma unroll
            for (int nt4 = 0; nt4 < 4; nt4++) {
                unsigned b0, b1, b2, b3;
                asm volatile("ldmatrix.sync.aligned.m8n8.x4.trans.shared.b16 {%0,%1,%2,%3}, [%4];"
                             : "=r"(b0), "=r"(b1), "=r"(b2), "=r"(b3)
                             : "r"(b_addr + ks * (16 * WROWH * 2) + nt4 * 32));
                asm volatile("mma.sync.aligned.m16n8k16.row.col.f32.f16.f16.f32 "
                             "{%0,%1,%2,%3}, {%4,%5,%6,%7}, {%8,%9}, {%0,%1,%2,%3};"
                             : "+f"(c[2 * nt4][0]), "+f"(c[2 * nt4][1]), "+f"(c[2 * nt4][2]), "+f"(c[2 * nt4][3])
                             : "r"(a0), "r"(a1), "r"(a2), "r"(a3), "r"(b0), "r"(b1));
                asm volatile("mma.sync.aligned.m16n8k16.row.col.f32.f16.f16.f32 "
                             "{%0,%1,%2,%3}, {%4,%5,%6,%7}, {%8,%9}, {%0,%1,%2,%3};"
                             : "+f"(c[2 * nt4 + 1][0]), "+f"(c[2 * nt4 + 1][1]), "+f"(c[2 * nt4 + 1][2]), "+f"(c[2 * nt4 + 1][3])
                             : "r"(a0), "r"(a1), "r"(a2), "r"(a3), "r"(b2), "r"(b3));
            }
        }

        // epilogue: store h (fp16) + accumulate BN stats
        int row0 = tile0 + 16 * w + grp;
        int row1 = row0 + 8;
        bool v0 = row0 < N, v1 = row1 < N;
#pragma unroll
        for (int nt = 0; nt < 8; nt++) {
            int col = nt * 8 + tig * 2;
            if (v0) {
                *(unsigned*)(h_out + (size_t)row0 * D + col) = h2u(__floats2half2_rn(c[nt][0], c[nt][1]));
                sl[2 * nt]     += c[nt][0];
                ql[2 * nt]      = fmaf(c[nt][0], c[nt][0], ql[2 * nt]);
                sl[2 * nt + 1] += c[nt][1];
                ql[2 * nt + 1]  = fmaf(c[nt][1], c[nt][1], ql[2 * nt + 1]);
            }
            if (v1) {
                *(unsigned*)(h_out + (size_t)row1 * D + col) = h2u(__floats2half2_rn(c[nt][2], c[nt][3]));
                sl[2 * nt]     += c[nt][2];
                ql[2 * nt]      = fmaf(c[nt][2], c[nt][2], ql[2 * nt]);
                sl[2 * nt + 1] += c[nt][3];
                ql[2 * nt + 1]  = fmaf(c[nt][3], c[nt][3], ql[2 * nt + 1]);
            }
        }
    }

    // reduce stats over row-groups
#pragma unroll
    for (int off = 4; off <= 16; off <<= 1) {
#pragma unroll
        for (int i = 0; i < 16; i++) {
            sl[i] += __shfl_xor_sync(0xffffffffu, sl[i], off);
            ql[i] += __shfl_xor_sync(0xffffffffu, ql[i], off);
        }
    }
    if (lane < 4) {
#pragma unroll
        for (int nt = 0; nt < 8; nt++) {
            atomicAdd(&s_sum[nt * 8 + 2 * lane],     sl[2 * nt]);
            atomicAdd(&s_sum[nt * 8 + 2 * lane + 1], sl[2 * nt + 1]);
            atomicAdd(&s_sq[nt * 8 + 2 * lane],      ql[2 * nt]);
            atomicAdd(&s_sq[nt * 8 + 2 * lane + 1],  ql[2 * nt + 1]);
        }
    }
    __syncthreads();
    if (tid < 64) atomicAdd(&ssum_out[tid], s_sum[tid]);
    else if (tid < 128) atomicAdd(&ssq_out[tid - 64], s_sq[tid - 64]);
}

// ---------------- pooling + classifier (final BN+ReLU inline) ----------------
__global__ void __launch_bounds__(1024) k_pool(
    const __half* __restrict__ hfin, const int* __restrict__ batch, int N,
    const float* __restrict__ Wcls, const float* __restrict__ bcls,
    const float* __restrict__ ssum, const float* __restrict__ ssq,
    const float* __restrict__ gamma_p, const float* __restrict__ beta_p,
    float invN, float* __restrict__ out)
{
    __shared__ float s_pool[D];
    int g = blockIdx.x, tid = threadIdx.x;

    int lo = 0, hi = N;
    while (lo < hi) { int mid = (lo + hi) >> 1; if (batch[mid] < g) lo = mid + 1; else hi = mid; }
    int start = lo;
    hi = N;
    while (lo < hi) { int mid = (lo + hi) >> 1; if (batch[mid] < g + 1) lo = mid + 1; else hi = mid; }
    int end = lo;

    if (tid < D) s_pool[tid] = 0.f;
    __syncthreads();

    int col = tid & 63, rg = tid >> 6;
    float mean = ssum[col] * invN;
    float var = fmaf(-mean, mean, ssq[col] * invN);
    var = var < 0.f ? 0.f : var;
    float sc = gamma_p[col] * rsqrtf(var + BN_EPS);
    float sh_ = beta_p[col] - mean * sc;

    float p0 = 0.f, p1 = 0.f, p2 = 0.f, p3 = 0.f;
    int r = start + rg;
    for (; r + 48 < end; r += 64) {
        float a0 = __half2float(hfin[(size_t)(r     ) * D + col]);
        float a1 = __half2float(hfin[(size_t)(r + 16) * D + col]);
        float a2 = __half2float(hfin[(size_t)(r + 32) * D + col]);
        float a3 = __half2float(hfin[(size_t)(r + 48) * D + col]);
        p0 += fmaxf(fmaf(a0, sc, sh_), 0.f);
        p1 += fmaxf(fmaf(a1, sc, sh_), 0.f);
        p2 += fmaxf(fmaf(a2, sc, sh_), 0.f);
        p3 += fmaxf(fmaf(a3, sc, sh_), 0.f);
    }
    for (; r < end; r += 16)
        p0 += fmaxf(fmaf(__half2float(hfin[(size_t)r * D + col]), sc, sh_), 0.f);
    atomicAdd(&s_pool[col], ((p0 + p1) + (p2 + p3)));
    __syncthreads();

    float cnt = (float)(end - start);
    float denom = cnt > 1.f ? cnt : 1.f;
    if (tid < D) s_pool[tid] /= denom;
    __syncthreads();

    if (tid < 10) {
        float acc = bcls[tid];
#pragma unroll
        for (int d = 0; d < D; d++) acc = fmaf(s_pool[d], Wcls[d * 10 + tid], acc);
        out[g * 10 + tid] = acc;
    }
}

// ---------------- launch -----------------------------------------------------
extern "C" void kernel_launch(void* const* d_in, const int* in_sizes, int n_in,
                              void* d_out, int out_size)
{
    const float* x     = (const float*)d_in[0];
    const int*   ei    = (const int*)d_in[1];
    const int*   batch = (const int*)d_in[2];
    const float* Wrel  = (const float*)d_in[3];
    const float* brel  = (const float*)d_in[4];
    const float* Wroot = (const float*)d_in[5];
    const float* gamma = (const float*)d_in[6];
    const float* beta  = (const float*)d_in[7];
    const float* Wcls  = (const float*)d_in[8];
    const float* bcls  = (const float*)d_in[9];
    float* out = (float*)d_out;

    int N = in_sizes[0] / D;
    int E = in_sizes[1] / 2;
    int G = out_size / 10;
    int NB = (N + 1023) / 1024;
    float invN = 1.f / (float)N;
    int NTILES = (N + TILE - 1) / TILE;
    int GATHER_BLOCKS = (N * 32 + 255) / 256;
    int total8 = N * 8;
    int GEMM_BLOCKS = NTILES < 296 ? NTILES : 296;

    static int attr_done = 0;
    if (!attr_done) {
        cudaFuncSetAttribute(k_gemm<0>, cudaFuncAttributeMaxDynamicSharedMemorySize, SMEM_BYTES);
        cudaFuncSetAttribute(k_gemm<1>, cudaFuncAttributeMaxDynamicSharedMemorySize, SMEM_BYTES);
        attr_done = 1;
    }

    __half *xh, *hA, *hB;
    float *s0, *q0, *s1, *q1, *s2, *q2;
    cudaGetSymbolAddress((void**)&xh, g_xh);
    cudaGetSymbolAddress((void**)&hA, g_hA);
    cudaGetSymbolAddress((void**)&hB, g_hB);
    cudaGetSymbolAddress((void**)&s0, g_s0);
    cudaGetSymbolAddress((void**)&q0, g_q0);
    cudaGetSymbolAddress((void**)&s1, g_s1);
    cudaGetSymbolAddress((void**)&q1, g_q1);
    cudaGetSymbolAddress((void**)&s2, g_s2);
    cudaGetSymbolAddress((void**)&q2, g_q2);

    // K1: full CSR build + convert (internal grid barriers)
    k_csr<<<CSR_BLOCKS, 256>>>(x, ei, N, E, NB, total8);

    // layer 0: xh -> hA (stats -> s0/q0)
    k_gather<0><<<GATHER_BLOCKS, 256>>>(xh, nullptr, nullptr, nullptr, nullptr, invN, N);
    k_gemm<0><<<GEMM_BLOCKS, 256, SMEM_BYTES>>>(xh, hA, Wrel, brel, Wroot,
                                                nullptr, nullptr, nullptr, nullptr,
                                                s0, q0, invN, N);

    // layer 1: hA -> hB (BN from s0; stats -> s1)
    k_gather<1><<<GATHER_BLOCKS, 256>>>(hA, s0, q0, gamma, beta, invN, N);
    k_gemm<1><<<GEMM_BLOCKS, 256, SMEM_BYTES>>>(hA, hB, Wrel + 4096, brel + 64, Wroot + 4096,
                                                s0, q0, gamma, beta,
                                                s1, q1, invN, N);

    // layer 2: hB -> hA (BN from s1; stats -> s2)
    k_gather<1><<<GATHER_BLOCKS, 256>>>(hB, s1, q1, gamma + 64, beta + 64, invN, N);
    k_gemm<1><<<GEMM_BLOCKS, 256, SMEM_BYTES>>>(hB, hA, Wrel + 8192, brel + 128, Wroot + 8192,
                                                s1, q1, gamma + 64, beta + 64,
                                                s2, q2, invN, N);

    // pool (applies layer-2 BN+ReLU from s2/q2) + classifier
    k_pool<<<G, 1024>>>(hA, batch, N, Wcls, bcls,
                        s2, q2, gamma + 128, beta + 128, invN, out);
}

// round 14
// speedup vs baseline: 1.1482x; 1.0264x over previous
#include <cuda_runtime.h>
#include <cuda_fp16.h>

#define D 64
#define MAXN 100000
#define MAXE 1250000
#define BN_EPS 1e-5f
#define TILE 128
#define AROWH 136
#define WROWH 72

__device__ __forceinline__ __half2 u2h2(unsigned u) { return *reinterpret_cast<__half2*>(&u); }
__device__ __forceinline__ unsigned h2u(__half2 h) { return *reinterpret_cast<unsigned*>(&h); }

// ---------------- static device scratch -------------------------------------
__device__ int   g_deg[MAXN];          // zero at module load; re-zeroed by scan1 every run
__device__ int   g_rowptr[MAXN + 1];
__device__ int   g_cursor[MAXN + 1];
__device__ int   g_blocksums[256];
__device__ int   g_srcsorted[MAXE];
__device__ __align__(16) __half g_xh[(size_t)MAXN * D];
__device__ __align__(16) __half g_msg[(size_t)MAXN * D];
__device__ __align__(16) __half g_hA[(size_t)MAXN * D];
__device__ __align__(16) __half g_hB[(size_t)MAXN * D];
__device__ __align__(16) float g_s0[D];
__device__ __align__(16) float g_q0[D];
__device__ __align__(16) float g_s1[D];
__device__ __align__(16) float g_q1[D];
__device__ __align__(16) float g_s2[D];
__device__ __align__(16) float g_q2[D];
__device__ unsigned g_bar_cnt;   // monotonic, never reset

// ---------------- grid barrier (monotonic counter, wrap-safe) ----------------
__device__ __forceinline__ void grid_bar() {
    __syncthreads();
    if (threadIdx.x == 0) {
        __threadfence();
        unsigned t = atomicAdd(&g_bar_cnt, 1u);
        unsigned target = t - (t % gridDim.x) + gridDim.x;
        if ((t % gridDim.x) != gridDim.x - 1) {
            volatile unsigned* p = &g_bar_cnt;
            while ((int)(*p - target) < 0) __nanosleep(64);
        }
        __threadfence();
    }
    __syncthreads();
}

// ---------------- K_csr: convert + hist | scan1 | scan23 | bucket ------------
#define CSR_BLOCKS 392
__global__ void __launch_bounds__(256) k_csr(
    const float* __restrict__ x, const int* __restrict__ ei,
    int N, int E, int NB, int total8)
{
    __shared__ int ish[256];
    int tid = threadIdx.x;
    int gtid = blockIdx.x * 256 + tid;
    int gstride = gridDim.x * 256;

    // ---- phase A: convert x -> fp16, zero stats, histogram ----
    for (int i = gtid; i < total8; i += gstride) {
        float4 a = ((const float4*)x)[i * 2];
        float4 b = ((const float4*)x)[i * 2 + 1];
        uint4 o;
        o.x = h2u(__floats2half2_rn(a.x, a.y));
        o.y = h2u(__floats2half2_rn(a.z, a.w));
        o.z = h2u(__floats2half2_rn(b.x, b.y));
        o.w = h2u(__floats2half2_rn(b.z, b.w));
        ((uint4*)g_xh)[i] = o;
    }
    if (blockIdx.x == 0 && tid < D) {
        g_s0[tid] = 0.f; g_q0[tid] = 0.f;
        g_s1[tid] = 0.f; g_q1[tid] = 0.f;
        g_s2[tid] = 0.f; g_q2[tid] = 0.f;
    }
    for (int e = gtid; e < E; e += gstride)
        atomicAdd(&g_deg[ei[E + e]], 1);
    grid_bar();

    // ---- phase B: scan1 (read deg, RE-ZERO deg for next run, local scan) ----
    if (blockIdx.x < NB) {
        int base = blockIdx.x * 1024 + tid * 4;
        int v0 = 0, v1 = 0, v2 = 0, v3 = 0;
        if (base + 0 < N) { v0 = g_deg[base + 0]; g_deg[base + 0] = 0; }
        if (base + 1 < N) { v1 = g_deg[base + 1]; g_deg[base + 1] = 0; }
        if (base + 2 < N) { v2 = g_deg[base + 2]; g_deg[base + 2] = 0; }
        if (base + 3 < N) { v3 = g_deg[base + 3]; g_deg[base + 3] = 0; }
        int t0 = v0, t1 = t0 + v1, t2 = t1 + v2, t3 = t2 + v3;
        ish[tid] = t3;
        __syncthreads();
        for (int off = 1; off < 256; off <<= 1) {
            int a = (tid >= off) ? ish[tid - off] : 0;
            __syncthreads();
            ish[tid] += a;
            __syncthreads();
        }
        int excl = ish[tid] - t3;
        if (base + 0 < N) g_rowptr[base + 1] = excl + t0;
        if (base + 1 < N) g_rowptr[base + 2] = excl + t1;
        if (base + 2 < N) g_rowptr[base + 3] = excl + t2;
        if (base + 3 < N) g_rowptr[base + 4] = excl + t3;
        if (tid == 255) g_blocksums[blockIdx.x] = ish[255];
    }
    grid_bar();

    // ---- phase C: scan23 (rescan blocksums, apply offset, fill cursor) ----
    if (blockIdx.x < NB) {
        int v = (tid < NB) ? g_blocksums[tid] : 0;
        ish[tid] = v;
        __syncthreads();
        for (int off = 1; off < 256; off <<= 1) {
            int a = (tid >= off) ? ish[tid - off] : 0;
            __syncthreads();
            ish[tid] += a;
            __syncthreads();
        }
        int off = (blockIdx.x == 0) ? 0 : ish[blockIdx.x - 1];
        int base = blockIdx.x * 1024 + tid * 4;
#pragma unroll
        for (int i = 0; i < 4; i++) {
            int idx = base + i;
            if (idx < N) {
                int val = g_rowptr[idx + 1] + off;
                g_rowptr[idx + 1] = val;
                if (idx + 1 < N) g_cursor[idx + 1] = val;
            }
        }
        if (blockIdx.x == 0 && tid == 0) { g_rowptr[0] = 0; g_cursor[0] = 0; }
    }
    grid_bar();

    // ---- phase D: bucket ----
    for (int e = gtid; e < E; e += gstride) {
        int d = ei[E + e];
        int pos = atomicAdd(&g_cursor[d], 1);
        g_srcsorted[pos] = ei[e];
    }
}

// ---------------- gather: warp/node, block-shared BN, 4-deep load pipeline ---
template<int TF>
__global__ void __launch_bounds__(256) k_gather(
    const __half* __restrict__ x_src,
    const float* __restrict__ ssum, const float* __restrict__ ssq,
    const float* __restrict__ gamma_p, const float* __restrict__ beta_p,
    float invN, int N)
{
    __shared__ __half sbn_sc[D];
    __shared__ __half sbn_sh[D];

    int tid = threadIdx.x;
    int lane = tid & 31;

    // BN constants once per block (64 threads, 1 rsqrt each)
    if (TF) {
        if (tid < D) {
            float mean = ssum[tid] * invN;
            float var = fmaf(-mean, mean, ssq[tid] * invN);
            var = var < 0.f ? 0.f : var;
            float s = gamma_p[tid] * rsqrtf(var + BN_EPS);
            sbn_sc[tid] = __float2half_rn(s);
            sbn_sh[tid] = __float2half_rn(beta_p[tid] - mean * s);
        }
        __syncthreads();
    }

    int node = (blockIdx.x * blockDim.x + tid) >> 5;
    if (node >= N) return;
    int q = lane >> 3;      // neighbor sub-slot 0..3
    int c8 = lane & 7;      // column group of 8 halves

    __half2 sc2[4], sh2[4];
    if (TF) {
#pragma unroll
        for (int j = 0; j < 4; j++) {
            sc2[j] = ((const __half2*)sbn_sc)[c8 * 4 + j];
            sh2[j] = ((const __half2*)sbn_sh)[c8 * 4 + j];
        }
    }

    float acc[8];
#pragma unroll
    for (int j = 0; j < 8; j++) acc[j] = 0.f;

    const __half2 z2 = __float2half2_rn(0.f);
    int rs = g_rowptr[node], re = g_rowptr[node + 1];
    for (int base = rs; base < re; base += 32) {
        int jj = base + lane;
        int sj = (jj < re) ? g_srcsorted[jj] : 0;
        int cnt = min(32, re - base);

        __half2 h0 = z2, h1 = z2, h2 = z2, h3 = z2;
        for (int wave = 0; wave < 32; wave += 16) {
            if (wave >= cnt) break;
            // phase 1: issue 4 clamped loads back-to-back (MLP=4)
            uint4 r[4];
            bool val[4];
#pragma unroll
            for (int it = 0; it < 4; it++) {
                int i0 = wave + it * 4 + q;
                int s = __shfl_sync(0xffffffffu, sj, i0 & 31);
                val[it] = i0 < cnt;
                int ss = val[it] ? s : 0;   // clamp: row 0 (cached, discarded)
                r[it] = *(const uint4*)(x_src + (size_t)ss * D + c8 * 8);
            }
            // phase 2: accumulate (predicated)
#pragma unroll
            for (int it = 0; it < 4; it++) {
                if (val[it]) {
                    __half2 v0 = u2h2(r[it].x), v1 = u2h2(r[it].y);
                    __half2 v2 = u2h2(r[it].z), v3 = u2h2(r[it].w);
                    if (TF) {
                        v0 = __hmax2(__hfma2(v0, sc2[0], sh2[0]), z2);
                        v1 = __hmax2(__hfma2(v1, sc2[1], sh2[1]), z2);
                        v2 = __hmax2(__hfma2(v2, sc2[2], sh2[2]), z2);
                        v3 = __hmax2(__hfma2(v3, sc2[3], sh2[3]), z2);
                    }
                    h0 = __hadd2(h0, v0);
                    h1 = __hadd2(h1, v1);
                    h2 = __hadd2(h2, v2);
                    h3 = __hadd2(h3, v3);
                }
            }
        }
        // flush chunk to fp32
        float2 f0 = __half22float2(h0), f1 = __half22float2(h1);
        float2 f2 = __half22float2(h2), f3 = __half22float2(h3);
        acc[0] += f0.x; acc[1] += f0.y; acc[2] += f1.x; acc[3] += f1.y;
        acc[4] += f2.x; acc[5] += f2.y; acc[6] += f3.x; acc[7] += f3.y;
    }

#pragma unroll
    for (int off = 8; off <= 16; off <<= 1)
#pragma unroll
        for (int j = 0; j < 8; j++) acc[j] += __shfl_xor_sync(0xffffffffu, acc[j], off);

    if (lane < 8) {
        uint4 o;
        o.x = h2u(__floats2half2_rn(acc[0], acc[1]));
        o.y = h2u(__floats2half2_rn(acc[2], acc[3]));
        o.z = h2u(__floats2half2_rn(acc[4], acc[5]));
        o.w = h2u(__floats2half2_rn(acc[6], acc[7]));
        *(uint4*)(g_msg + (size_t)node * D + lane * 8) = o;
    }
}

// ---------------- tensor-core GEMM: [msg|x](Nx128) @ [Wrel;Wroot](128x64) -----
#define SMEM_A_BYTES (128 * AROWH * 2)
#define SMEM_W_OFF   SMEM_A_BYTES
#define SMEM_F_OFF   (SMEM_A_BYTES + 128 * WROWH * 2)
#define SMEM_BYTES   (SMEM_F_OFF + 64 * 4 * 3 + 64 * 2 * 2)

template<int TF>
__global__ void __launch_bounds__(256) k_gemm(
    const __half* __restrict__ x_src, __half* __restrict__ h_out,
    const float* __restrict__ Wrel, const float* __restrict__ brel,
    const float* __restrict__ Wroot,
    const float* __restrict__ ssum_in, const float* __restrict__ ssq_in,
    const float* __restrict__ gamma_p, const float* __restrict__ beta_p,
    float* __restrict__ ssum_out, float* __restrict__ ssq_out,
    float invN, int N)
{
    extern __shared__ char smemc[];
    __half* a_sh = (__half*)smemc;
    __half* w_sh = (__half*)(smemc + SMEM_W_OFF);
    float* s_bias = (float*)(smemc + SMEM_F_OFF);
    float* s_sum = s_bias + 64;
    float* s_sq  = s_sum + 64;
    __half* s_sch = (__half*)(s_sq + 64);
    __half* s_shh = s_sch + 64;

    int tid = threadIdx.x;
    int lane = tid & 31;
    int w = tid >> 5;

    // stage W (fp32 -> fp16) once per block
    for (int i = tid; i < 1024; i += 256) {
        int k = i >> 4, n4 = (i & 15) * 4;
        float4 v = ((const float4*)Wrel)[i];
        uint2 hv;
        hv.x = h2u(__floats2half2_rn(v.x, v.y));
        hv.y = h2u(__floats2half2_rn(v.z, v.w));
        *(uint2*)(w_sh + k * WROWH + n4) = hv;
        float4 u = ((const float4*)Wroot)[i];
        uint2 hu;
        hu.x = h2u(__floats2half2_rn(u.x, u.y));
        hu.y = h2u(__floats2half2_rn(u.z, u.w));
        *(uint2*)(w_sh + (64 + k) * WROWH + n4) = hu;
    }
    if (tid < 64) {
        s_bias[tid] = brel[tid];
        s_sum[tid] = 0.f;
        s_sq[tid] = 0.f;
        if (TF) {
            float mean = ssum_in[tid] * invN;
            float var = fmaf(-mean, mean, ssq_in[tid] * invN);
            var = var < 0.f ? 0.f : var;
            float s = gamma_p[tid] * rsqrtf(var + BN_EPS);
            s_sch[tid] = __float2half_rn(s);
            s_shh[tid] = __float2half_rn(beta_p[tid] - mean * s);
        }
    }

    unsigned sbase = (unsigned)__cvta_generic_to_shared(smemc);
    unsigned a_addr = sbase + ((16 * w + (lane & 15)) * AROWH + ((lane >> 4) << 3)) * 2;
    unsigned b_addr = sbase + SMEM_W_OFF + ((lane & 15) * WROWH + ((lane >> 4) << 3)) * 2;

    int grp = lane >> 2, tig = lane & 3;
    float sl[16], ql[16];
#pragma unroll
    for (int i = 0; i < 16; i++) { sl[i] = 0.f; ql[i] = 0.f; }

    int ntiles = (N + TILE - 1) / TILE;
    for (int tile = blockIdx.x; tile < ntiles; tile += gridDim.x) {
        int tile0 = tile * TILE;
        __syncthreads();

        // stage A = [msg | x] rows (fp16): 128 rows x 16 uint4 (128 halves/row)
        for (int i = tid; i < 2048; i += 256) {
            int r = i >> 4, seg = i & 15;
            int node = tile0 + r;
            uint4 val = make_uint4(0u, 0u, 0u, 0u);
            if (node < N) {
                if (seg < 8) {
                    val = ((const uint4*)(g_msg + (size_t)node * D))[seg];
                } else {
                    val = ((const uint4*)(x_src + (size_t)node * D))[seg - 8];
                    if (TF) {
                        int cb2 = (seg - 8) * 4;
                        const __half2* scp = (const __half2*)s_sch;
                        const __half2* shp = (const __half2*)s_shh;
                        __half2 z = __float2half2_rn(0.f);
                        val.x = h2u(__hmax2(__hfma2(u2h2(val.x), scp[cb2 + 0], shp[cb2 + 0]), z));
                        val.y = h2u(__hmax2(__hfma2(u2h2(val.y), scp[cb2 + 1], shp[cb2 + 1]), z));
                        val.z = h2u(__hmax2(__hfma2(u2h2(val.z), scp[cb2 + 2], shp[cb2 + 2]), z));
                        val.w = h2u(__hmax2(__hfma2(u2h2(val.w), scp[cb2 + 3], shp[cb2 + 3]), z));
                    }
                }
            }
            *(uint4*)(a_sh + r * AROWH + seg * 8) = val;
        }
        __syncthreads();

        // accumulators (init with bias)
        float c[8][4];
#pragma unroll
        for (int nt = 0; nt < 8; nt++) {
            float b0 = s_bias[nt * 8 + tig * 2];
            float b1 = s_bias[nt * 8 + tig * 2 + 1];
            c[nt][0] = b0; c[nt][1] = b1; c[nt][2] = b0; c[nt][3] = b1;
        }

#pragma unroll
        for (int ks = 0; ks < 8; ks++) {
            unsigned a0, a1, a2, a3;
            asm volatile("ldmatrix.sync.aligned.m8n8.x4.shared.b16 {%0,%1,%2,%3}, [%4];"
                         : "=r"(a0), "=r"(a1), "=r"(a2), "=r"(a3)
                         : "r"(a_addr + ks * 32));
#pragma unroll
            for (int nt4 = 0; nt4 < 4; nt4++) {
                unsigned b0, b1, b2, b3;
                asm volatile("ldmatrix.sync.aligned.m8n8.x4.trans.shared.b16 {%0,%1,%2,%3}, [%4];"
                             : "=r"(b0), "=r"(b1), "=r"(b2), "=r"(b3)
                             : "r"(b_addr + ks * (16 * WROWH * 2) + nt4 * 32));
                asm volatile("mma.sync.aligned.m16n8k16.row.col.f32.f16.f16.f32 "
                             "{%0,%1,%2,%3}, {%4,%5,%6,%7}, {%8,%9}, {%0,%1,%2,%3};"
                             : "+f"(c[2 * nt4][0]), "+f"(c[2 * nt4][1]), "+f"(c[2 * nt4][2]), "+f"(c[2 * nt4][3])
                             : "r"(a0), "r"(a1), "r"(a2), "r"(a3), "r"(b0), "r"(b1));
                asm volatile("mma.sync.aligned.m16n8k16.row.col.f32.f16.f16.f32 "
                             "{%0,%1,%2,%3}, {%4,%5,%6,%7}, {%8,%9}, {%0,%1,%2,%3};"
                             : "+f"(c[2 * nt4 + 1][0]), "+f"(c[2 * nt4 + 1][1]), "+f"(c[2 * nt4 + 1][2]), "+f"(c[2 * nt4 + 1][3])
                             : "r"(a0), "r"(a1), "r"(a2), "r"(a3), "r"(b2), "r"(b3));
            }
        }

        // epilogue: store h (fp16) + accumulate BN stats
        int row0 = tile0 + 16 * w + grp;
        int row1 = row0 + 8;
        bool v0 = row0 < N, v1 = row1 < N;
#pragma unroll
        for (int nt = 0; nt < 8; nt++) {
            int col = nt * 8 + tig * 2;
            if (v0) {
                *(unsigned*)(h_out + (size_t)row0 * D + col) = h2u(__floats2half2_rn(c[nt][0], c[nt][1]));
                sl[2 * nt]     += c[nt][0];
                ql[2 * nt]      = fmaf(c[nt][0], c[nt][0], ql[2 * nt]);
                sl[2 * nt + 1] += c[nt][1];
                ql[2 * nt + 1]  = fmaf(c[nt][1], c[nt][1], ql[2 * nt + 1]);
            }
            if (v1) {
                *(unsigned*)(h_out + (size_t)row1 * D + col) = h2u(__floats2half2_rn(c[nt][2], c[nt][3]));
                sl[2 * nt]     += c[nt][2];
                ql[2 * nt]      = fmaf(c[nt][2], c[nt][2], ql[2 * nt]);
                sl[2 * nt + 1] += c[nt][3];
                ql[2 * nt + 1]  = fmaf(c[nt][3], c[nt][3], ql[2 * nt + 1]);
            }
        }
    }

    // reduce stats over row-groups
#pragma unroll
    for (int off = 4; off <= 16; off <<= 1) {
#pragma unroll
        for (int i = 0; i < 16; i++) {
            sl[i] += __shfl_xor_sync(0xffffffffu, sl[i], off);
            ql[i] += __shfl_xor_sync(0xffffffffu, ql[i], off);
        }
    }
    if (lane < 4) {
#pragma unroll
        for (int nt = 0; nt < 8; nt++) {
            atomicAdd(&s_sum[nt * 8 + 2 * lane],     sl[2 * nt]);
            atomicAdd(&s_sum[nt * 8 + 2 * lane + 1], sl[2 * nt + 1]);
            atomicAdd(&s_sq[nt * 8 + 2 * lane],      ql[2 * nt]);
            atomicAdd(&s_sq[nt * 8 + 2 * lane + 1],  ql[2 * nt + 1]);
        }
    }
    __syncthreads();
    if (tid < 64) atomicAdd(&ssum_out[tid], s_sum[tid]);
    else if (tid < 128) atomicAdd(&ssq_out[tid - 64], s_sq[tid - 64]);
}

// ---------------- pooling + classifier (final BN+ReLU inline) ----------------
__global__ void __launch_bounds__(1024) k_pool(
    const __half* __restrict__ hfin, const int* __restrict__ batch, int N,
    const float* __restrict__ Wcls, const float* __restrict__ bcls,
    const float* __restrict__ ssum, const float* __restrict__ ssq,
    const float* __restrict__ gamma_p, const float* __restrict__ beta_p,
    float invN, float* __restrict__ out)
{
    __shared__ float s_pool[D];
    int g = blockIdx.x, tid = threadIdx.x;

    int lo = 0, hi = N;
    while (lo < hi) { int mid = (lo + hi) >> 1; if (batch[mid] < g) lo = mid + 1; else hi = mid; }
    int start = lo;
    hi = N;
    while (lo < hi) { int mid = (lo + hi) >> 1; if (batch[mid] < g + 1) lo = mid + 1; else hi = mid; }
    int end = lo;

    if (tid < D) s_pool[tid] = 0.f;
    __syncthreads();

    int col = tid & 63, rg = tid >> 6;
    float mean = ssum[col] * invN;
    float var = fmaf(-mean, mean, ssq[col] * invN);
    var = var < 0.f ? 0.f : var;
    float sc = gamma_p[col] * rsqrtf(var + BN_EPS);
    float sh_ = beta_p[col] - mean * sc;

    float p0 = 0.f, p1 = 0.f, p2 = 0.f, p3 = 0.f;
    int r = start + rg;
    for (; r + 48 < end; r += 64) {
        float a0 = __half2float(hfin[(size_t)(r     ) * D + col]);
        float a1 = __half2float(hfin[(size_t)(r + 16) * D + col]);
        float a2 = __half2float(hfin[(size_t)(r + 32) * D + col]);
        float a3 = __half2float(hfin[(size_t)(r + 48) * D + col]);
        p0 += fmaxf(fmaf(a0, sc, sh_), 0.f);
        p1 += fmaxf(fmaf(a1, sc, sh_), 0.f);
        p2 += fmaxf(fmaf(a2, sc, sh_), 0.f);
        p3 += fmaxf(fmaf(a3, sc, sh_), 0.f);
    }
    for (; r < end; r += 16)
        p0 += fmaxf(fmaf(__half2float(hfin[(size_t)r * D + col]), sc, sh_), 0.f);
    atomicAdd(&s_pool[col], ((p0 + p1) + (p2 + p3)));
    __syncthreads();

    float cnt = (float)(end - start);
    float denom = cnt > 1.f ? cnt : 1.f;
    if (tid < D) s_pool[tid] /= denom;
    __syncthreads();

    if (tid < 10) {
        float acc = bcls[tid];
#pragma unroll
        for (int d = 0; d < D; d++) acc = fmaf(s_pool[d], Wcls[d * 10 + tid], acc);
        out[g * 10 + tid] = acc;
    }
}

// ---------------- launch -----------------------------------------------------
extern "C" void kernel_launch(void* const* d_in, const int* in_sizes, int n_in,
                              void* d_out, int out_size)
{
    const float* x     = (const float*)d_in[0];
    const int*   ei    = (const int*)d_in[1];
    const int*   batch = (const int*)d_in[2];
    const float* Wrel  = (const float*)d_in[3];
    const float* brel  = (const float*)d_in[4];
    const float* Wroot = (const float*)d_in[5];
    const float* gamma = (const float*)d_in[6];
    const float* beta  = (const float*)d_in[7];
    const float* Wcls  = (const float*)d_in[8];
    const float* bcls  = (const float*)d_in[9];
    float* out = (float*)d_out;

    int N = in_sizes[0] / D;
    int E = in_sizes[1] / 2;
    int G = out_size / 10;
    int NB = (N + 1023) / 1024;
    float invN = 1.f / (float)N;
    int NTILES = (N + TILE - 1) / TILE;
    int GATHER_BLOCKS = (N * 32 + 255) / 256;
    int total8 = N * 8;
    int GEMM_BLOCKS = NTILES < 296 ? NTILES : 296;

    static int attr_done = 0;
    if (!attr_done) {
        cudaFuncSetAttribute(k_gemm<0>, cudaFuncAttributeMaxDynamicSharedMemorySize, SMEM_BYTES);
        cudaFuncSetAttribute(k_gemm<1>, cudaFuncAttributeMaxDynamicSharedMemorySize, SMEM_BYTES);
        attr_done = 1;
    }

    __half *xh, *hA, *hB;
    float *s0, *q0, *s1, *q1, *s2, *q2;
    cudaGetSymbolAddress((void**)&xh, g_xh);
    cudaGetSymbolAddress((void**)&hA, g_hA);
    cudaGetSymbolAddress((void**)&hB, g_hB);
    cudaGetSymbolAddress((void**)&s0, g_s0);
    cudaGetSymbolAddress((void**)&q0, g_q0);
    cudaGetSymbolAddress((void**)&s1, g_s1);
    cudaGetSymbolAddress((void**)&q1, g_q1);
    cudaGetSymbolAddress((void**)&s2, g_s2);
    cudaGetSymbolAddress((void**)&q2, g_q2);

    // K1: full CSR build + convert (internal grid barriers)
    k_csr<<<CSR_BLOCKS, 256>>>(x, ei, N, E, NB, total8);

    // layer 0: xh -> hA (stats -> s0/q0)
    k_gather<0><<<GATHER_BLOCKS, 256>>>(xh, nullptr, nullptr, nullptr, nullptr, invN, N);
    k_gemm<0><<<GEMM_BLOCKS, 256, SMEM_BYTES>>>(xh, hA, Wrel, brel, Wroot,
                                                nullptr, nullptr, nullptr, nullptr,
                                                s0, q0, invN, N);

    // layer 1: hA -> hB (BN from s0; stats -> s1)
    k_gather<1><<<GATHER_BLOCKS, 256>>>(hA, s0, q0, gamma, beta, invN, N);
    k_gemm<1><<<GEMM_BLOCKS, 256, SMEM_BYTES>>>(hA, hB, Wrel + 4096, brel + 64, Wroot + 4096,
                                                s0, q0, gamma, beta,
                                                s1, q1, invN, N);

    // layer 2: hB -> hA (BN from s1; stats -> s2)
    k_gather<1><<<GATHER_BLOCKS, 256>>>(hB, s1, q1, gamma + 64, beta + 64, invN, N);
    k_gemm<1><<<GEMM_BLOCKS, 256, SMEM_BYTES>>>(hB, hA, Wrel + 8192, brel + 128, Wroot + 8192,
                                                s1, q1, gamma + 64, beta + 64,
                                                s2, q2, invN, N);

    // pool (applies layer-2 BN+ReLU from s2/q2) + classifier
    k_pool<<<G, 1024>>>(hA, batch, N, Wcls, bcls,
                        s2, q2, gamma + 128, beta + 128, invN, out);
}

// round 15
// speedup vs baseline: 1.1684x; 1.0176x over previous
#include <cuda_runtime.h>
#include <cuda_fp16.h>

#define D 64
#define MAXN 100000
#define MAXE 1250000
#define BN_EPS 1e-5f
#define TILE 128
#define AROWH 136
#define WROWH 72

__device__ __forceinline__ __half2 u2h2(unsigned u) { return *reinterpret_cast<__half2*>(&u); }
__device__ __forceinline__ unsigned h2u(__half2 h) { return *reinterpret_cast<unsigned*>(&h); }

// ---------------- static device scratch -------------------------------------
__device__ int   g_deg[MAXN];          // zero at module load; re-zeroed by scan1 every run
__device__ int   g_rowptr[MAXN + 1];
__device__ int   g_cursor[MAXN + 1];
__device__ int   g_blocksums[256];
__device__ int   g_srcsorted[MAXE];
__device__ __align__(16) __half g_xh[(size_t)MAXN * D];
__device__ __align__(16) __half g_msg[(size_t)MAXN * D];
__device__ __align__(16) __half g_hA[(size_t)MAXN * D];
__device__ __align__(16) __half g_hB[(size_t)MAXN * D];
__device__ __align__(16) float g_s0[D];
__device__ __align__(16) float g_q0[D];
__device__ __align__(16) float g_s1[D];
__device__ __align__(16) float g_q1[D];
__device__ __align__(16) float g_s2[D];
__device__ __align__(16) float g_q2[D];
__device__ unsigned g_bar_cnt;   // monotonic, never reset

// ---------------- grid barrier (monotonic counter, wrap-safe) ----------------
__device__ __forceinline__ void grid_bar() {
    __syncthreads();
    if (threadIdx.x == 0) {
        __threadfence();
        unsigned t = atomicAdd(&g_bar_cnt, 1u);
        unsigned target = t - (t % gridDim.x) + gridDim.x;
        if ((t % gridDim.x) != gridDim.x - 1) {
            volatile unsigned* p = &g_bar_cnt;
            while ((int)(*p - target) < 0) __nanosleep(64);
        }
        __threadfence();
    }
    __syncthreads();
}

// ---------------- K_csr: convert + hist | scan1 | scan23 | bucket ------------
#define CSR_BLOCKS 392
__global__ void __launch_bounds__(256) k_csr(
    const float* __restrict__ x, const int* __restrict__ ei,
    int N, int E, int NB, int total8)
{
    __shared__ int ish[256];
    int tid = threadIdx.x;
    int gtid = blockIdx.x * 256 + tid;
    int gstride = gridDim.x * 256;

    // ---- phase A: convert x -> fp16, zero stats, histogram ----
    for (int i = gtid; i < total8; i += gstride) {
        float4 a = ((const float4*)x)[i * 2];
        float4 b = ((const float4*)x)[i * 2 + 1];
        uint4 o;
        o.x = h2u(__floats2half2_rn(a.x, a.y));
        o.y = h2u(__floats2half2_rn(a.z, a.w));
        o.z = h2u(__floats2half2_rn(b.x, b.y));
        o.w = h2u(__floats2half2_rn(b.z, b.w));
        ((uint4*)g_xh)[i] = o;
    }
    if (blockIdx.x == 0 && tid < D) {
        g_s0[tid] = 0.f; g_q0[tid] = 0.f;
        g_s1[tid] = 0.f; g_q1[tid] = 0.f;
        g_s2[tid] = 0.f; g_q2[tid] = 0.f;
    }
    for (int e = gtid; e < E; e += gstride)
        atomicAdd(&g_deg[ei[E + e]], 1);
    grid_bar();

    // ---- phase B: scan1 (read deg, RE-ZERO deg for next run, local scan) ----
    if (blockIdx.x < NB) {
        int base = blockIdx.x * 1024 + tid * 4;
        int v0 = 0, v1 = 0, v2 = 0, v3 = 0;
        if (base + 0 < N) { v0 = g_deg[base + 0]; g_deg[base + 0] = 0; }
        if (base + 1 < N) { v1 = g_deg[base + 1]; g_deg[base + 1] = 0; }
        if (base + 2 < N) { v2 = g_deg[base + 2]; g_deg[base + 2] = 0; }
        if (base + 3 < N) { v3 = g_deg[base + 3]; g_deg[base + 3] = 0; }
        int t0 = v0, t1 = t0 + v1, t2 = t1 + v2, t3 = t2 + v3;
        ish[tid] = t3;
        __syncthreads();
        for (int off = 1; off < 256; off <<= 1) {
            int a = (tid >= off) ? ish[tid - off] : 0;
            __syncthreads();
            ish[tid] += a;
            __syncthreads();
        }
        int excl = ish[tid] - t3;
        if (base + 0 < N) g_rowptr[base + 1] = excl + t0;
        if (base + 1 < N) g_rowptr[base + 2] = excl + t1;
        if (base + 2 < N) g_rowptr[base + 3] = excl + t2;
        if (base + 3 < N) g_rowptr[base + 4] = excl + t3;
        if (tid == 255) g_blocksums[blockIdx.x] = ish[255];
    }
    grid_bar();

    // ---- phase C: scan23 (rescan blocksums, apply offset, fill cursor) ----
    if (blockIdx.x < NB) {
        int v = (tid < NB) ? g_blocksums[tid] : 0;
        ish[tid] = v;
        __syncthreads();
        for (int off = 1; off < 256; off <<= 1) {
            int a = (tid >= off) ? ish[tid - off] : 0;
            __syncthreads();
            ish[tid] += a;
            __syncthreads();
        }
        int off = (blockIdx.x == 0) ? 0 : ish[blockIdx.x - 1];
        int base = blockIdx.x * 1024 + tid * 4;
#pragma unroll
        for (int i = 0; i < 4; i++) {
            int idx = base + i;
            if (idx < N) {
                int val = g_rowptr[idx + 1] + off;
                g_rowptr[idx + 1] = val;
                if (idx + 1 < N) g_cursor[idx + 1] = val;
            }
        }
        if (blockIdx.x == 0 && tid == 0) { g_rowptr[0] = 0; g_cursor[0] = 0; }
    }
    grid_bar();

    // ---- phase D: bucket ----
    for (int e = gtid; e < E; e += gstride) {
        int d = ei[E + e];
        int pos = atomicAdd(&g_cursor[d], 1);
        g_srcsorted[pos] = ei[e];
    }
}

// ---------------- gather: warp/node, high-occ + 4-deep load pipeline ---------
template<int TF>
__global__ void __launch_bounds__(256, 6) k_gather(
    const __half* __restrict__ x_src,
    const float* __restrict__ ssum, const float* __restrict__ ssq,
    const float* __restrict__ gamma_p, const float* __restrict__ beta_p,
    float invN, int N)
{
    __shared__ __half sbn_sc[D];
    __shared__ __half sbn_sh[D];

    int tid = threadIdx.x;
    int lane = tid & 31;
    int node = (blockIdx.x * blockDim.x + tid) >> 5;

    // issue rowptr loads early (overlaps BN staging + syncthreads)
    int rs = 0, re = 0;
    if (node < N) { rs = g_rowptr[node]; re = g_rowptr[node + 1]; }

    // BN constants once per block (64 threads, 1 rsqrt each)
    if (TF) {
        if (tid < D) {
            float mean = ssum[tid] * invN;
            float var = fmaf(-mean, mean, ssq[tid] * invN);
            var = var < 0.f ? 0.f : var;
            float s = gamma_p[tid] * rsqrtf(var + BN_EPS);
            sbn_sc[tid] = __float2half_rn(s);
            sbn_sh[tid] = __float2half_rn(beta_p[tid] - mean * s);
        }
        __syncthreads();
    }
    if (node >= N) return;

    int q = lane >> 3;      // neighbor sub-slot 0..3
    int c8 = lane & 7;      // column group of 8 halves

    __half2 sc2[4], sh2[4];
    if (TF) {
#pragma unroll
        for (int j = 0; j < 4; j++) {
            sc2[j] = ((const __half2*)sbn_sc)[c8 * 4 + j];
            sh2[j] = ((const __half2*)sbn_sh)[c8 * 4 + j];
        }
    }

    float acc[8];
#pragma unroll
    for (int j = 0; j < 8; j++) acc[j] = 0.f;

    const __half2 z2 = __float2half2_rn(0.f);
    for (int base = rs; base < re; base += 32) {
        int jj = base + lane;
        int sj = (jj < re) ? g_srcsorted[jj] : 0;
        int cnt = min(32, re - base);

        for (int wave = 0; wave < 32; wave += 16) {
            if (wave >= cnt) break;
            // phase 1: issue 4 clamped loads back-to-back (MLP=4)
            uint4 r[4];
            bool val[4];
#pragma unroll
            for (int it = 0; it < 4; it++) {
                int i0 = wave + it * 4 + q;
                int s = __shfl_sync(0xffffffffu, sj, i0 & 31);
                val[it] = i0 < cnt;
                int ss = val[it] ? s : 0;   // clamp: row 0 (cached, discarded)
                r[it] = *(const uint4*)(x_src + (size_t)ss * D + c8 * 8);
            }
            // phase 2: accumulate into fp32 (predicated)
#pragma unroll
            for (int it = 0; it < 4; it++) {
                if (val[it]) {
                    __half2 v0 = u2h2(r[it].x), v1 = u2h2(r[it].y);
                    __half2 v2 = u2h2(r[it].z), v3 = u2h2(r[it].w);
                    if (TF) {
                        v0 = __hmax2(__hfma2(v0, sc2[0], sh2[0]), z2);
                        v1 = __hmax2(__hfma2(v1, sc2[1], sh2[1]), z2);
                        v2 = __hmax2(__hfma2(v2, sc2[2], sh2[2]), z2);
                        v3 = __hmax2(__hfma2(v3, sc2[3], sh2[3]), z2);
                    }
                    float2 f0 = __half22float2(v0), f1 = __half22float2(v1);
                    float2 f2 = __half22float2(v2), f3 = __half22float2(v3);
                    acc[0] += f0.x; acc[1] += f0.y; acc[2] += f1.x; acc[3] += f1.y;
                    acc[4] += f2.x; acc[5] += f2.y; acc[6] += f3.x; acc[7] += f3.y;
                }
            }
        }
    }

#pragma unroll
    for (int off = 8; off <= 16; off <<= 1)
#pragma unroll
        for (int j = 0; j < 8; j++) acc[j] += __shfl_xor_sync(0xffffffffu, acc[j], off);

    if (lane < 8) {
        uint4 o;
        o.x = h2u(__floats2half2_rn(acc[0], acc[1]));
        o.y = h2u(__floats2half2_rn(acc[2], acc[3]));
        o.z = h2u(__floats2half2_rn(acc[4], acc[5]));
        o.w = h2u(__floats2half2_rn(acc[6], acc[7]));
        *(uint4*)(g_msg + (size_t)node * D + lane * 8) = o;
    }
}

// ---------------- tensor-core GEMM: [msg|x](Nx128) @ [Wrel;Wroot](128x64) -----
#define SMEM_A_BYTES (128 * AROWH * 2)
#define SMEM_W_OFF   SMEM_A_BYTES
#define SMEM_F_OFF   (SMEM_A_BYTES + 128 * WROWH * 2)
#define SMEM_BYTES   (SMEM_F_OFF + 64 * 4 * 3 + 64 * 2 * 2)

template<int TF>
__global__ void __launch_bounds__(256) k_gemm(
    const __half* __restrict__ x_src, __half* __restrict__ h_out,
    const float* __restrict__ Wrel, const float* __restrict__ brel,
    const float* __restrict__ Wroot,
    const float* __restrict__ ssum_in, const float* __restrict__ ssq_in,
    const float* __restrict__ gamma_p, const float* __restrict__ beta_p,
    float* __restrict__ ssum_out, float* __restrict__ ssq_out,
    float invN, int N)
{
    extern __shared__ char smemc[];
    __half* a_sh = (__half*)smemc;
    __half* w_sh = (__half*)(smemc + SMEM_W_OFF);
    float* s_bias = (float*)(smemc + SMEM_F_OFF);
    float* s_sum = s_bias + 64;
    float* s_sq  = s_sum + 64;
    __half* s_sch = (__half*)(s_sq + 64);
    __half* s_shh = s_sch + 64;

    int tid = threadIdx.x;
    int lane = tid & 31;
    int w = tid >> 5;

    // stage W (fp32 -> fp16) once per block
    for (int i = tid; i < 1024; i += 256) {
        int k = i >> 4, n4 = (i & 15) * 4;
        float4 v = ((const float4*)Wrel)[i];
        uint2 hv;
        hv.x = h2u(__floats2half2_rn(v.x, v.y));
        hv.y = h2u(__floats2half2_rn(v.z, v.w));
        *(uint2*)(w_sh + k * WROWH + n4) = hv;
        float4 u = ((const float4*)Wroot)[i];
        uint2 hu;
        hu.x = h2u(__floats2half2_rn(u.x, u.y));
        hu.y = h2u(__floats2half2_rn(u.z, u.w));
        *(uint2*)(w_sh + (64 + k) * WROWH + n4) = hu;
    }
    if (tid < 64) {
        s_bias[tid] = brel[tid];
        s_sum[tid] = 0.f;
        s_sq[tid] = 0.f;
        if (TF) {
            float mean = ssum_in[tid] * invN;
            float var = fmaf(-mean, mean, ssq_in[tid] * invN);
            var = var < 0.f ? 0.f : var;
            float s = gamma_p[tid] * rsqrtf(var + BN_EPS);
            s_sch[tid] = __float2half_rn(s);
            s_shh[tid] = __float2half_rn(beta_p[tid] - mean * s);
        }
    }

    unsigned sbase = (unsigned)__cvta_generic_to_shared(smemc);
    unsigned a_addr = sbase + ((16 * w + (lane & 15)) * AROWH + ((lane >> 4) << 3)) * 2;
    unsigned b_addr = sbase + SMEM_W_OFF + ((lane & 15) * WROWH + ((lane >> 4) << 3)) * 2;

    int grp = lane >> 2, tig = lane & 3;
    float sl[16], ql[16];
#pragma unroll
    for (int i = 0; i < 16; i++) { sl[i] = 0.f; ql[i] = 0.f; }

    int ntiles = (N + TILE - 1) / TILE;
    for (int tile = blockIdx.x; tile < ntiles; tile += gridDim.x) {
        int tile0 = tile * TILE;
        __syncthreads();

        // stage A = [msg | x] rows (fp16): 128 rows x 16 uint4 (128 halves/row)
        for (int i = tid; i < 2048; i += 256) {
            int r = i >> 4, seg = i & 15;
            int node = tile0 + r;
            uint4 val = make_uint4(0u, 0u, 0u, 0u);
            if (node < N) {
                if (seg < 8) {
                    val = ((const uint4*)(g_msg + (size_t)node * D))[seg];
                } else {
                    val = ((const uint4*)(x_src + (size_t)node * D))[seg - 8];
                    if (TF) {
                        int cb2 = (seg - 8) * 4;
                        const __half2* scp = (const __half2*)s_sch;
                        const __half2* shp = (const __half2*)s_shh;
                        __half2 z = __float2half2_rn(0.f);
                        val.x = h2u(__hmax2(__hfma2(u2h2(val.x), scp[cb2 + 0], shp[cb2 + 0]), z));
                        val.y = h2u(__hmax2(__hfma2(u2h2(val.y), scp[cb2 + 1], shp[cb2 + 1]), z));
                        val.z = h2u(__hmax2(__hfma2(u2h2(val.z), scp[cb2 + 2], shp[cb2 + 2]), z));
                        val.w = h2u(__hmax2(__hfma2(u2h2(val.w), scp[cb2 + 3], shp[cb2 + 3]), z));
                    }
                }
            }
            *(uint4*)(a_sh + r * AROWH + seg * 8) = val;
        }
        __syncthreads();

        // accumulators (init with bias)
        float c[8][4];
#pragma unroll
        for (int nt = 0; nt < 8; nt++) {
            float b0 = s_bias[nt * 8 + tig * 2];
            float b1 = s_bias[nt * 8 + tig * 2 + 1];
            c[nt][0] = b0; c[nt][1] = b1; c[nt][2] = b0; c[nt][3] = b1;
        }

#pragma unroll
        for (int ks = 0; ks < 8; ks++) {
            unsigned a0, a1, a2, a3;
            asm volatile("ldmatrix.sync.aligned.m8n8.x4.shared.b16 {%0,%1,%2,%3}, [%4];"
                         : "=r"(a0), "=r"(a1), "=r"(a2), "=r"(a3)
                         : "r"(a_addr + ks * 32));
#pragma unroll
            for (int nt4 = 0; nt4 < 4; nt4++) {
                unsigned b0, b1, b2, b3;
                asm volatile("ldmatrix.sync.aligned.m8n8.x4.trans.shared.b16 {%0,%1,%2,%3}, [%4];"
                             : "=r"(b0), "=r"(b1), "=r"(b2), "=r"(b3)
                             : "r"(b_addr + ks * (16 * WROWH * 2) + nt4 * 32));
                asm volatile("mma.sync.aligned.m16n8k16.row.col.f32.f16.f16.f32 "
                             "{%0,%1,%2,%3}, {%4,%5,%6,%7}, {%8,%9}, {%0,%1,%2,%3};"
                             : "+f"(c[2 * nt4][0]), "+f"(c[2 * nt4][1]), "+f"(c[2 * nt4][2]), "+f"(c[2 * nt4][3])
                             : "r"(a0), "r"(a1), "r"(a2), "r"(a3), "r"(b0), "r"(b1));
                asm volatile("mma.sync.aligned.m16n8k16.row.col.f32.f16.f16.f32 "
                             "{%0,%1,%2,%3}, {%4,%5,%6,%7}, {%8,%9}, {%0,%1,%2,%3};"
                             : "+f"(c[2 * nt4 + 1][0]), "+f"(c[2 * nt4 + 1][1]), "+f"(c[2 * nt4 + 1][2]), "+f"(c[2 * nt4 + 1][3])
                             : "r"(a0), "r"(a1), "r"(a2), "r"(a3), "r"(b2), "r"(b3));
            }
        }

        // epilogue: store h (fp16) + accumulate BN stats
        int row0 = tile0 + 16 * w + grp;
        int row1 = row0 + 8;
        bool v0 = row0 < N, v1 = row1 < N;
#pragma unroll
        for (int nt = 0; nt < 8; nt++) {
            int col = nt * 8 + tig * 2;
            if (v0) {
                *(unsigned*)(h_out + (size_t)row0 * D + col) = h2u(__floats2half2_rn(c[nt][0], c[nt][1]));
                sl[2 * nt]     += c[nt][0];
                ql[2 * nt]      = fmaf(c[nt][0], c[nt][0], ql[2 * nt]);
                sl[2 * nt + 1] += c[nt][1];
                ql[2 * nt + 1]  = fmaf(c[nt][1], c[nt][1], ql[2 * nt + 1]);
            }
            if (v1) {
                *(unsigned*)(h_out + (size_t)row1 * D + col) = h2u(__floats2half2_rn(c[nt][2], c[nt][3]));
                sl[2 * nt]     += c[nt][2];
                ql[2 * nt]      = fmaf(c[nt][2], c[nt][2], ql[2 * nt]);
                sl[2 * nt + 1] += c[nt][3];
                ql[2 * nt + 1]  = fmaf(c[nt][3], c[nt][3], ql[2 * nt + 1]);
            }
        }
    }

    // reduce stats over row-groups
#pragma unroll
    for (int off = 4; off <= 16; off <<= 1) {
#pragma unroll
        for (int i = 0; i < 16; i++) {
            sl[i] += __shfl_xor_sync(0xffffffffu, sl[i], off);
            ql[i] += __shfl_xor_sync(0xffffffffu, ql[i], off);
        }
    }
    if (lane < 4) {
#pragma unroll
        for (int nt = 0; nt < 8; nt++) {
            atomicAdd(&s_sum[nt * 8 + 2 * lane],     sl[2 * nt]);
            atomicAdd(&s_sum[nt * 8 + 2 * lane + 1], sl[2 * nt + 1]);
            atomicAdd(&s_sq[nt * 8 + 2 * lane],      ql[2 * nt]);
            atomicAdd(&s_sq[nt * 8 + 2 * lane + 1],  ql[2 * nt + 1]);
        }
    }
    __syncthreads();
    if (tid < 64) atomicAdd(&ssum_out[tid], s_sum[tid]);
    else if (tid < 128) atomicAdd(&ssq_out[tid - 64], s_sq[tid - 64]);
}

// ---------------- pooling + classifier (final BN+ReLU inline) ----------------
__global__ void __launch_bounds__(1024) k_pool(
    const __half* __restrict__ hfin, const int* __restrict__ batch, int N,
    const float* __restrict__ Wcls, const float* __restrict__ bcls,
    const float* __restrict__ ssum, const float* __restrict__ ssq,
    const float* __restrict__ gamma_p, const float* __restrict__ beta_p,
    float invN, float* __restrict__ out)
{
    __shared__ float s_pool[D];
    int g = blockIdx.x, tid = threadIdx.x;

    int lo = 0, hi = N;
    while (lo < hi) { int mid = (lo + hi) >> 1; if (batch[mid] < g) lo = mid + 1; else hi = mid; }
    int start = lo;
    hi = N;
    while (lo < hi) { int mid = (lo + hi) >> 1; if (batch[mid] < g + 1) lo = mid + 1; else hi = mid; }
    int end = lo;

    if (tid < D) s_pool[tid] = 0.f;
    __syncthreads();

    int col = tid & 63, rg = tid >> 6;
    float mean = ssum[col] * invN;
    float var = fmaf(-mean, mean, ssq[col] * invN);
    var = var < 0.f ? 0.f : var;
    float sc = gamma_p[col] * rsqrtf(var + BN_EPS);
    float sh_ = beta_p[col] - mean * sc;

    float p0 = 0.f, p1 = 0.f, p2 = 0.f, p3 = 0.f;
    int r = start + rg;
    for (; r + 48 < end; r += 64) {
        float a0 = __half2float(hfin[(size_t)(r     ) * D + col]);
        float a1 = __half2float(hfin[(size_t)(r + 16) * D + col]);
        float a2 = __half2float(hfin[(size_t)(r + 32) * D + col]);
        float a3 = __half2float(hfin[(size_t)(r + 48) * D + col]);
        p0 += fmaxf(fmaf(a0, sc, sh_), 0.f);
        p1 += fmaxf(fmaf(a1, sc, sh_), 0.f);
        p2 += fmaxf(fmaf(a2, sc, sh_), 0.f);
        p3 += fmaxf(fmaf(a3, sc, sh_), 0.f);
    }
    for (; r < end; r += 16)
        p0 += fmaxf(fmaf(__half2float(hfin[(size_t)r * D + col]), sc, sh_), 0.f);
    atomicAdd(&s_pool[col], ((p0 + p1) + (p2 + p3)));
    __syncthreads();

    float cnt = (float)(end - start);
    float denom = cnt > 1.f ? cnt : 1.f;
    if (tid < D) s_pool[tid] /= denom;
    __syncthreads();

    if (tid < 10) {
        float acc = bcls[tid];
#pragma unroll
        for (int d = 0; d < D; d++) acc = fmaf(s_pool[d], Wcls[d * 10 + tid], acc);
        out[g * 10 + tid] = acc;
    }
}

// ---------------- launch -----------------------------------------------------
extern "C" void kernel_launch(void* const* d_in, const int* in_sizes, int n_in,
                              void* d_out, int out_size)
{
    const float* x     = (const float*)d_in[0];
    const int*   ei    = (const int*)d_in[1];
    const int*   batch = (const int*)d_in[2];
    const float* Wrel  = (const float*)d_in[3];
    const float* brel  = (const float*)d_in[4];
    const float* Wroot = (const float*)d_in[5];
    const float* gamma = (const float*)d_in[6];
    const float* beta  = (const float*)d_in[7];
    const float* Wcls  = (const float*)d_in[8];
    const float* bcls  = (const float*)d_in[9];
    float* out = (float*)d_out;

    int N = in_sizes[0] / D;
    int E = in_sizes[1] / 2;
    int G = out_size / 10;
    int NB = (N + 1023) / 1024;
    float invN = 1.f / (float)N;
    int NTILES = (N + TILE - 1) / TILE;
    int GATHER_BLOCKS = (N * 32 + 255) / 256;
    int total8 = N * 8;
    int GEMM_BLOCKS = NTILES < 296 ? NTILES : 296;

    static int attr_done = 0;
    if (!attr_done) {
        cudaFuncSetAttribute(k_gemm<0>, cudaFuncAttributeMaxDynamicSharedMemorySize, SMEM_BYTES);
        cudaFuncSetAttribute(k_gemm<1>, cudaFuncAttributeMaxDynamicSharedMemorySize, SMEM_BYTES);
        attr_done = 1;
    }

    __half *xh, *hA, *hB;
    float *s0, *q0, *s1, *q1, *s2, *q2;
    cudaGetSymbolAddress((void**)&xh, g_xh);
    cudaGetSymbolAddress((void**)&hA, g_hA);
    cudaGetSymbolAddress((void**)&hB, g_hB);
    cudaGetSymbolAddress((void**)&s0, g_s0);
    cudaGetSymbolAddress((void**)&q0, g_q0);
    cudaGetSymbolAddress((void**)&s1, g_s1);
    cudaGetSymbolAddress((void**)&q1, g_q1);
    cudaGetSymbolAddress((void**)&s2, g_s2);
    cudaGetSymbolAddress((void**)&q2, g_q2);

    // K1: full CSR build + convert (internal grid barriers)
    k_csr<<<CSR_BLOCKS, 256>>>(x, ei, N, E, NB, total8);

    // layer 0: xh -> hA (stats -> s0/q0)
    k_gather<0><<<GATHER_BLOCKS, 256>>>(xh, nullptr, nullptr, nullptr, nullptr, invN, N);
    k_gemm<0><<<GEMM_BLOCKS, 256, SMEM_BYTES>>>(xh, hA, Wrel, brel, Wroot,
                                                nullptr, nullptr, nullptr, nullptr,
                                                s0, q0, invN, N);

    // layer 1: hA -> hB (BN from s0; stats -> s1)
    k_gather<1><<<GATHER_BLOCKS, 256>>>(hA, s0, q0, gamma, beta, invN, N);
    k_gemm<1><<<GEMM_BLOCKS, 256, SMEM_BYTES>>>(hA, hB, Wrel + 4096, brel + 64, Wroot + 4096,
                                                s0, q0, gamma, beta,
                                                s1, q1, invN, N);

    // layer 2: hB -> hA (BN from s1; stats -> s2)
    k_gather<1><<<GATHER_BLOCKS, 256>>>(hB, s1, q1, gamma + 64, beta + 64, invN, N);
    k_gemm<1><<<GEMM_BLOCKS, 256, SMEM_BYTES>>>(hB, hA, Wrel + 8192, brel + 128, Wroot + 8192,
                                                s1, q1, gamma + 64, beta + 64,
                                                s2, q2, invN, N);

    // pool (applies layer-2 BN+ReLU from s2/q2) + classifier
    k_pool<<<G, 1024>>>(hA, batch, N, Wcls, bcls,
                        s2, q2, gamma + 128, beta + 128, invN, out);
}

// round 16
// speedup vs baseline: 1.1898x; 1.0183x over previous
#include <cuda_runtime.h>
#include <cuda_fp16.h>

#define D 64
#define MAXN 100000
#define MAXE 1250000
#define BN_EPS 1e-5f
#define TILE 128
#define AROWH 136
#define WROWH 72

__device__ __forceinline__ __half2 u2h2(unsigned u) { return *reinterpret_cast<__half2*>(&u); }
__device__ __forceinline__ unsigned h2u(__half2 h) { return *reinterpret_cast<unsigned*>(&h); }

// ---------------- static device scratch -------------------------------------
__device__ int   g_deg[MAXN];          // zero at module load; re-zeroed by scan1 every run
__device__ int   g_rowptr[MAXN + 1];
__device__ int   g_cursor[MAXN + 1];
__device__ int   g_blocksums[256];
__device__ int   g_srcsorted[MAXE];
__device__ __align__(16) __half g_xh[(size_t)MAXN * D];
__device__ __align__(16) __half g_msg[(size_t)MAXN * D];
__device__ __align__(16) __half g_hA[(size_t)MAXN * D];
__device__ __align__(16) __half g_hB[(size_t)MAXN * D];
__device__ __align__(16) float g_s0[D];
__device__ __align__(16) float g_q0[D];
__device__ __align__(16) float g_s1[D];
__device__ __align__(16) float g_q1[D];
__device__ __align__(16) float g_s2[D];
__device__ __align__(16) float g_q2[D];
__device__ unsigned g_bar_cnt;   // monotonic, never reset

// ---------------- grid barrier (monotonic counter, wrap-safe) ----------------
__device__ __forceinline__ void grid_bar() {
    __syncthreads();
    if (threadIdx.x == 0) {
        __threadfence();
        unsigned t = atomicAdd(&g_bar_cnt, 1u);
        unsigned target = t - (t % gridDim.x) + gridDim.x;
        if ((t % gridDim.x) != gridDim.x - 1) {
            volatile unsigned* p = &g_bar_cnt;
            while ((int)(*p - target) < 0) __nanosleep(64);
        }
        __threadfence();
    }
    __syncthreads();
}

// ---------------- K_csr: convert + hist | scan1 | scan23 | bucket ------------
#define CSR_BLOCKS 392
__global__ void __launch_bounds__(256) k_csr(
    const float* __restrict__ x, const int* __restrict__ ei,
    int N, int E, int NB, int total8)
{
    __shared__ int ish[256];
    int tid = threadIdx.x;
    int gtid = blockIdx.x * 256 + tid;
    int gstride = gridDim.x * 256;

    // ---- phase A: convert x -> fp16, zero stats, histogram ----
    for (int i = gtid; i < total8; i += gstride) {
        float4 a = ((const float4*)x)[i * 2];
        float4 b = ((const float4*)x)[i * 2 + 1];
        uint4 o;
        o.x = h2u(__floats2half2_rn(a.x, a.y));
        o.y = h2u(__floats2half2_rn(a.z, a.w));
        o.z = h2u(__floats2half2_rn(b.x, b.y));
        o.w = h2u(__floats2half2_rn(b.z, b.w));
        ((uint4*)g_xh)[i] = o;
    }
    if (blockIdx.x == 0 && tid < D) {
        g_s0[tid] = 0.f; g_q0[tid] = 0.f;
        g_s1[tid] = 0.f; g_q1[tid] = 0.f;
        g_s2[tid] = 0.f; g_q2[tid] = 0.f;
    }
    for (int e = gtid; e < E; e += gstride)
        atomicAdd(&g_deg[ei[E + e]], 1);
    grid_bar();

    // ---- phase B: scan1 (read deg, RE-ZERO deg for next run, local scan) ----
    if (blockIdx.x < NB) {
        int base = blockIdx.x * 1024 + tid * 4;
        int v0 = 0, v1 = 0, v2 = 0, v3 = 0;
        if (base + 0 < N) { v0 = g_deg[base + 0]; g_deg[base + 0] = 0; }
        if (base + 1 < N) { v1 = g_deg[base + 1]; g_deg[base + 1] = 0; }
        if (base + 2 < N) { v2 = g_deg[base + 2]; g_deg[base + 2] = 0; }
        if (base + 3 < N) { v3 = g_deg[base + 3]; g_deg[base + 3] = 0; }
        int t0 = v0, t1 = t0 + v1, t2 = t1 + v2, t3 = t2 + v3;
        ish[tid] = t3;
        __syncthreads();
        for (int off = 1; off < 256; off <<= 1) {
            int a = (tid >= off) ? ish[tid - off] : 0;
            __syncthreads();
            ish[tid] += a;
            __syncthreads();
        }
        int excl = ish[tid] - t3;
        if (base + 0 < N) g_rowptr[base + 1] = excl + t0;
        if (base + 1 < N) g_rowptr[base + 2] = excl + t1;
        if (base + 2 < N) g_rowptr[base + 3] = excl + t2;
        if (base + 3 < N) g_rowptr[base + 4] = excl + t3;
        if (tid == 255) g_blocksums[blockIdx.x] = ish[255];
    }
    grid_bar();

    // ---- phase C: scan23 (rescan blocksums, apply offset, fill cursor) ----
    if (blockIdx.x < NB) {
        int v = (tid < NB) ? g_blocksums[tid] : 0;
        ish[tid] = v;
        __syncthreads();
        for (int off = 1; off < 256; off <<= 1) {
            int a = (tid >= off) ? ish[tid - off] : 0;
            __syncthreads();
            ish[tid] += a;
            __syncthreads();
        }
        int off = (blockIdx.x == 0) ? 0 : ish[blockIdx.x - 1];
        int base = blockIdx.x * 1024 + tid * 4;
#pragma unroll
        for (int i = 0; i < 4; i++) {
            int idx = base + i;
            if (idx < N) {
                int val = g_rowptr[idx + 1] + off;
                g_rowptr[idx + 1] = val;
                if (idx + 1 < N) g_cursor[idx + 1] = val;
            }
        }
        if (blockIdx.x == 0 && tid == 0) { g_rowptr[0] = 0; g_cursor[0] = 0; }
    }
    grid_bar();

    // ---- phase D: bucket ----
    for (int e = gtid; e < E; e += gstride) {
        int d = ei[E + e];
        int pos = atomicAdd(&g_cursor[d], 1);
        g_srcsorted[pos] = ei[e];
    }
}

// ---------------- gather: MLP-4 pipeline + fp16 chunk accumulation ----------
template<int TF>
__global__ void __launch_bounds__(256, 5) k_gather(
    const __half* __restrict__ x_src,
    const float* __restrict__ ssum, const float* __restrict__ ssq,
    const float* __restrict__ gamma_p, const float* __restrict__ beta_p,
    float invN, int N)
{
    __shared__ __half sbn_sc[D];
    __shared__ __half sbn_sh[D];

    int tid = threadIdx.x;
    int lane = tid & 31;
    int node = (blockIdx.x * blockDim.x + tid) >> 5;

    // issue rowptr loads early (overlaps BN staging + syncthreads)
    int rs = 0, re = 0;
    if (node < N) { rs = g_rowptr[node]; re = g_rowptr[node + 1]; }

    // BN constants once per block (64 threads, 1 rsqrt each)
    if (TF) {
        if (tid < D) {
            float mean = ssum[tid] * invN;
            float var = fmaf(-mean, mean, ssq[tid] * invN);
            var = var < 0.f ? 0.f : var;
            float s = gamma_p[tid] * rsqrtf(var + BN_EPS);
            sbn_sc[tid] = __float2half_rn(s);
            sbn_sh[tid] = __float2half_rn(beta_p[tid] - mean * s);
        }
        __syncthreads();
    }
    if (node >= N) return;

    int q = lane >> 3;      // neighbor sub-slot 0..3
    int c8 = lane & 7;      // column group of 8 halves

    __half2 sc2[4], sh2[4];
    if (TF) {
#pragma unroll
        for (int j = 0; j < 4; j++) {
            sc2[j] = ((const __half2*)sbn_sc)[c8 * 4 + j];
            sh2[j] = ((const __half2*)sbn_sh)[c8 * 4 + j];
        }
    }

    float acc[8];
#pragma unroll
    for (int j = 0; j < 8; j++) acc[j] = 0.f;

    const __half2 z2 = __float2half2_rn(0.f);
    for (int base = rs; base < re; base += 32) {
        int jj = base + lane;
        int sj = (jj < re) ? g_srcsorted[jj] : 0;
        int cnt = min(32, re - base);

        // fp16 chunk accumulators (<=8 adds each per chunk)
        __half2 h0 = z2, h1 = z2, h2 = z2, h3 = z2;
        for (int wave = 0; wave < 32; wave += 16) {
            if (wave >= cnt) break;
            // phase 1: issue 4 clamped loads back-to-back (MLP=4)
            uint4 r[4];
            bool val[4];
#pragma unroll
            for (int it = 0; it < 4; it++) {
                int i0 = wave + it * 4 + q;
                int s = __shfl_sync(0xffffffffu, sj, i0 & 31);
                val[it] = i0 < cnt;
                int ss = val[it] ? s : 0;   // clamp: row 0 (cached, discarded)
                r[it] = *(const uint4*)(x_src + (size_t)ss * D + c8 * 8);
            }
            // phase 2: fp16 accumulate (predicated)
#pragma unroll
            for (int it = 0; it < 4; it++) {
                if (val[it]) {
                    __half2 v0 = u2h2(r[it].x), v1 = u2h2(r[it].y);
                    __half2 v2 = u2h2(r[it].z), v3 = u2h2(r[it].w);
                    if (TF) {
                        v0 = __hmax2(__hfma2(v0, sc2[0], sh2[0]), z2);
                        v1 = __hmax2(__hfma2(v1, sc2[1], sh2[1]), z2);
                        v2 = __hmax2(__hfma2(v2, sc2[2], sh2[2]), z2);
                        v3 = __hmax2(__hfma2(v3, sc2[3], sh2[3]), z2);
                    }
                    h0 = __hadd2(h0, v0);
                    h1 = __hadd2(h1, v1);
                    h2 = __hadd2(h2, v2);
                    h3 = __hadd2(h3, v3);
                }
            }
        }
        // flush chunk to fp32
        float2 f0 = __half22float2(h0), f1 = __half22float2(h1);
        float2 f2 = __half22float2(h2), f3 = __half22float2(h3);
        acc[0] += f0.x; acc[1] += f0.y; acc[2] += f1.x; acc[3] += f1.y;
        acc[4] += f2.x; acc[5] += f2.y; acc[6] += f3.x; acc[7] += f3.y;
    }

#pragma unroll
    for (int off = 8; off <= 16; off <<= 1)
#pragma unroll
        for (int j = 0; j < 8; j++) acc[j] += __shfl_xor_sync(0xffffffffu, acc[j], off);

    if (lane < 8) {
        uint4 o;
        o.x = h2u(__floats2half2_rn(acc[0], acc[1]));
        o.y = h2u(__floats2half2_rn(acc[2], acc[3]));
        o.z = h2u(__floats2half2_rn(acc[4], acc[5]));
        o.w = h2u(__floats2half2_rn(acc[6], acc[7]));
        *(uint4*)(g_msg + (size_t)node * D + lane * 8) = o;
    }
}

// ---------------- tensor-core GEMM: [msg|x](Nx128) @ [Wrel;Wroot](128x64) -----
#define SMEM_A_BYTES (128 * AROWH * 2)
#define SMEM_W_OFF   SMEM_A_BYTES
#define SMEM_F_OFF   (SMEM_A_BYTES + 128 * WROWH * 2)
#define SMEM_BYTES   (SMEM_F_OFF + 64 * 4 * 3 + 64 * 2 * 2)

template<int TF>
__global__ void __launch_bounds__(256) k_gemm(
    const __half* __restrict__ x_src, __half* __restrict__ h_out,
    const float* __restrict__ Wrel, const float* __restrict__ brel,
    const float* __restrict__ Wroot,
    const float* __restrict__ ssum_in, const float* __restrict__ ssq_in,
    const float* __restrict__ gamma_p, const float* __restrict__ beta_p,
    float* __restrict__ ssum_out, float* __restrict__ ssq_out,
    float invN, int N)
{
    extern __shared__ char smemc[];
    __half* a_sh = (__half*)smemc;
    __half* w_sh = (__half*)(smemc + SMEM_W_OFF);
    float* s_bias = (float*)(smemc + SMEM_F_OFF);
    float* s_sum = s_bias + 64;
    float* s_sq  = s_sum + 64;
    __half* s_sch = (__half*)(s_sq + 64);
    __half* s_shh = s_sch + 64;

    int tid = threadIdx.x;
    int lane = tid & 31;
    int w = tid >> 5;

    // stage W (fp32 -> fp16) once per block
    for (int i = tid; i < 1024; i += 256) {
        int k = i >> 4, n4 = (i & 15) * 4;
        float4 v = ((const float4*)Wrel)[i];
        uint2 hv;
        hv.x = h2u(__floats2half2_rn(v.x, v.y));
        hv.y = h2u(__floats2half2_rn(v.z, v.w));
        *(uint2*)(w_sh + k * WROWH + n4) = hv;
        float4 u = ((const float4*)Wroot)[i];
        uint2 hu;
        hu.x = h2u(__floats2half2_rn(u.x, u.y));
        hu.y = h2u(__floats2half2_rn(u.z, u.w));
        *(uint2*)(w_sh + (64 + k) * WROWH + n4) = hu;
    }
    if (tid < 64) {
        s_bias[tid] = brel[tid];
        s_sum[tid] = 0.f;
        s_sq[tid] = 0.f;
        if (TF) {
            float mean = ssum_in[tid] * invN;
            float var = fmaf(-mean, mean, ssq_in[tid] * invN);
            var = var < 0.f ? 0.f : var;
            float s = gamma_p[tid] * rsqrtf(var + BN_EPS);
            s_sch[tid] = __float2half_rn(s);
            s_shh[tid] = __float2half_rn(beta_p[tid] - mean * s);
        }
    }

    unsigned sbase = (unsigned)__cvta_generic_to_shared(smemc);
    unsigned a_addr = sbase + ((16 * w + (lane & 15)) * AROWH + ((lane >> 4) << 3)) * 2;
    unsigned b_addr = sbase + SMEM_W_OFF + ((lane & 15) * WROWH + ((lane >> 4) << 3)) * 2;

    int grp = lane >> 2, tig = lane & 3;
    float sl[16], ql[16];
#pragma unroll
    for (int i = 0; i < 16; i++) { sl[i] = 0.f; ql[i] = 0.f; }

    int ntiles = (N + TILE - 1) / TILE;
    for (int tile = blockIdx.x; tile < ntiles; tile += gridDim.x) {
        int tile0 = tile * TILE;
        __syncthreads();

        // stage A = [msg | x] rows (fp16): 128 rows x 16 uint4 (128 halves/row)
        for (int i = tid; i < 2048; i += 256) {
            int r = i >> 4, seg = i & 15;
            int node = tile0 + r;
            uint4 val = make_uint4(0u, 0u, 0u, 0u);
            if (node < N) {
                if (seg < 8) {
                    val = ((const uint4*)(g_msg + (size_t)node * D))[seg];
                } else {
                    val = ((const uint4*)(x_src + (size_t)node * D))[seg - 8];
                    if (TF) {
                        int cb2 = (seg - 8) * 4;
                        const __half2* scp = (const __half2*)s_sch;
                        const __half2* shp = (const __half2*)s_shh;
                        __half2 z = __float2half2_rn(0.f);
                        val.x = h2u(__hmax2(__hfma2(u2h2(val.x), scp[cb2 + 0], shp[cb2 + 0]), z));
                        val.y = h2u(__hmax2(__hfma2(u2h2(val.y), scp[cb2 + 1], shp[cb2 + 1]), z));
                        val.z = h2u(__hmax2(__hfma2(u2h2(val.z), scp[cb2 + 2], shp[cb2 + 2]), z));
                        val.w = h2u(__hmax2(__hfma2(u2h2(val.w), scp[cb2 + 3], shp[cb2 + 3]), z));
                    }
                }
            }
            *(uint4*)(a_sh + r * AROWH + seg * 8) = val;
        }
        __syncthreads();

        // accumulators (init with bias)
        float c[8][4];
#pragma unroll
        for (int nt = 0; nt < 8; nt++) {
            float b0 = s_bias[nt * 8 + tig * 2];
            float b1 = s_bias[nt * 8 + tig * 2 + 1];
            c[nt][0] = b0; c[nt][1] = b1; c[nt][2] = b0; c[nt][3] = b1;
        }

#pragma unroll
        for (int ks = 0; ks < 8; ks++) {
            unsigned a0, a1, a2, a3;
            asm volatile("ldmatrix.sync.aligned.m8n8.x4.shared.b16 {%0,%1,%2,%3}, [%4];"
                         : "=r"(a0), "=r"(a1), "=r"(a2), "=r"(a3)
                         : "r"(a_addr + ks * 32));
#pragma unroll
            for (int nt4 = 0; nt4 < 4; nt4++) {
                unsigned b0, b1, b2, b3;
                asm volatile("ldmatrix.sync.aligned.m8n8.x4.trans.shared.b16 {%0,%1,%2,%3}, [%4];"
                             : "=r"(b0), "=r"(b1), "=r"(b2), "=r"(b3)
                             : "r"(b_addr + ks * (16 * WROWH * 2) + nt4 * 32));
                asm volatile("mma.sync.aligned.m16n8k16.row.col.f32.f16.f16.f32 "
                             "{%0,%1,%2,%3}, {%4,%5,%6,%7}, {%8,%9}, {%0,%1,%2,%3};"
                             : "+f"(c[2 * nt4][0]), "+f"(c[2 * nt4][1]), "+f"(c[2 * nt4][2]), "+f"(c[2 * nt4][3])
                             : "r"(a0), "r"(a1), "r"(a2), "r"(a3), "r"(b0), "r"(b1));
                asm volatile("mma.sync.aligned.m16n8k16.row.col.f32.f16.f16.f32 "
                             "{%0,%1,%2,%3}, {%4,%5,%6,%7}, {%8,%9}, {%0,%1,%2,%3};"
                             : "+f"(c[2 * nt4 + 1][0]), "+f"(c[2 * nt4 + 1][1]), "+f"(c[2 * nt4 + 1][2]), "+f"(c[2 * nt4 + 1][3])
                             : "r"(a0), "r"(a1), "r"(a2), "r"(a3), "r"(b2), "r"(b3));
            }
        }

        // epilogue: store h (fp16) + accumulate BN stats
        int row0 = tile0 + 16 * w + grp;
        int row1 = row0 + 8;
        bool v0 = row0 < N, v1 = row1 < N;
#pragma unroll
        for (int nt = 0; nt < 8; nt++) {
            int col = nt * 8 + tig * 2;
            if (v0) {
                *(unsigned*)(h_out + (size_t)row0 * D + col) = h2u(__floats2half2_rn(c[nt][0], c[nt][1]));
                sl[2 * nt]     += c[nt][0];
                ql[2 * nt]      = fmaf(c[nt][0], c[nt][0], ql[2 * nt]);
                sl[2 * nt + 1] += c[nt][1];
                ql[2 * nt + 1]  = fmaf(c[nt][1], c[nt][1], ql[2 * nt + 1]);
            }
            if (v1) {
                *(unsigned*)(h_out + (size_t)row1 * D + col) = h2u(__floats2half2_rn(c[nt][2], c[nt][3]));
                sl[2 * nt]     += c[nt][2];
                ql[2 * nt]      = fmaf(c[nt][2], c[nt][2], ql[2 * nt]);
                sl[2 * nt + 1] += c[nt][3];
                ql[2 * nt + 1]  = fmaf(c[nt][3], c[nt][3], ql[2 * nt + 1]);
            }
        }
    }

    // reduce stats over row-groups
#pragma unroll
    for (int off = 4; off <= 16; off <<= 1) {
#pragma unroll
        for (int i = 0; i < 16; i++) {
            sl[i] += __shfl_xor_sync(0xffffffffu, sl[i], off);
            ql[i] += __shfl_xor_sync(0xffffffffu, ql[i], off);
        }
    }
    if (lane < 4) {
#pragma unroll
        for (int nt = 0; nt < 8; nt++) {
            atomicAdd(&s_sum[nt * 8 + 2 * lane],     sl[2 * nt]);
            atomicAdd(&s_sum[nt * 8 + 2 * lane + 1], sl[2 * nt + 1]);
            atomicAdd(&s_sq[nt * 8 + 2 * lane],      ql[2 * nt]);
            atomicAdd(&s_sq[nt * 8 + 2 * lane + 1],  ql[2 * nt + 1]);
        }
    }
    __syncthreads();
    if (tid < 64) atomicAdd(&ssum_out[tid], s_sum[tid]);
    else if (tid < 128) atomicAdd(&ssq_out[tid - 64], s_sq[tid - 64]);
}

// ---------------- pooling + classifier (final BN+ReLU inline) ----------------
__global__ void __launch_bounds__(1024) k_pool(
    const __half* __restrict__ hfin, const int* __restrict__ batch, int N,
    const float* __restrict__ Wcls, const float* __restrict__ bcls,
    const float* __restrict__ ssum, const float* __restrict__ ssq,
    const float* __restrict__ gamma_p, const float* __restrict__ beta_p,
    float invN, float* __restrict__ out)
{
    __shared__ float s_pool[D];
    int g = blockIdx.x, tid = threadIdx.x;

    int lo = 0, hi = N;
    while (lo < hi) { int mid = (lo + hi) >> 1; if (batch[mid] < g) lo = mid + 1; else hi = mid; }
    int start = lo;
    hi = N;
    while (lo < hi) { int mid = (lo + hi) >> 1; if (batch[mid] < g + 1) lo = mid + 1; else hi = mid; }
    int end = lo;

    if (tid < D) s_pool[tid] = 0.f;
    __syncthreads();

    int col = tid & 63, rg = tid >> 6;
    float mean = ssum[col] * invN;
    float var = fmaf(-mean, mean, ssq[col] * invN);
    var = var < 0.f ? 0.f : var;
    float sc = gamma_p[col] * rsqrtf(var + BN_EPS);
    float sh_ = beta_p[col] - mean * sc;

    float p0 = 0.f, p1 = 0.f, p2 = 0.f, p3 = 0.f;
    int r = start + rg;
    for (; r + 48 < end; r += 64) {
        float a0 = __half2float(hfin[(size_t)(r     ) * D + col]);
        float a1 = __half2float(hfin[(size_t)(r + 16) * D + col]);
        float a2 = __half2float(hfin[(size_t)(r + 32) * D + col]);
        float a3 = __half2float(hfin[(size_t)(r + 48) * D + col]);
        p0 += fmaxf(fmaf(a0, sc, sh_), 0.f);
        p1 += fmaxf(fmaf(a1, sc, sh_), 0.f);
        p2 += fmaxf(fmaf(a2, sc, sh_), 0.f);
        p3 += fmaxf(fmaf(a3, sc, sh_), 0.f);
    }
    for (; r < end; r += 16)
        p0 += fmaxf(fmaf(__half2float(hfin[(size_t)r * D + col]), sc, sh_), 0.f);
    atomicAdd(&s_pool[col], ((p0 + p1) + (p2 + p3)));
    __syncthreads();

    float cnt = (float)(end - start);
    float denom = cnt > 1.f ? cnt : 1.f;
    if (tid < D) s_pool[tid] /= denom;
    __syncthreads();

    if (tid < 10) {
        float acc = bcls[tid];
#pragma unroll
        for (int d = 0; d < D; d++) acc = fmaf(s_pool[d], Wcls[d * 10 + tid], acc);
        out[g * 10 + tid] = acc;
    }
}

// ---------------- launch -----------------------------------------------------
extern "C" void kernel_launch(void* const* d_in, const int* in_sizes, int n_in,
                              void* d_out, int out_size)
{
    const float* x     = (const float*)d_in[0];
    const int*   ei    = (const int*)d_in[1];
    const int*   batch = (const int*)d_in[2];
    const float* Wrel  = (const float*)d_in[3];
    const float* brel  = (const float*)d_in[4];
    const float* Wroot = (const float*)d_in[5];
    const float* gamma = (const float*)d_in[6];
    const float* beta  = (const float*)d_in[7];
    const float* Wcls  = (const float*)d_in[8];
    const float* bcls  = (const float*)d_in[9];
    float* out = (float*)d_out;

    int N = in_sizes[0] / D;
    int E = in_sizes[1] / 2;
    int G = out_size / 10;
    int NB = (N + 1023) / 1024;
    float invN = 1.f / (float)N;
    int NTILES = (N + TILE - 1) / TILE;
    int GATHER_BLOCKS = (N * 32 + 255) / 256;
    int total8 = N * 8;
    int GEMM_BLOCKS = NTILES < 296 ? NTILES : 296;

    static int attr_done = 0;
    if (!attr_done) {
        cudaFuncSetAttribute(k_gemm<0>, cudaFuncAttributeMaxDynamicSharedMemorySize, SMEM_BYTES);
        cudaFuncSetAttribute(k_gemm<1>, cudaFuncAttributeMaxDynamicSharedMemorySize, SMEM_BYTES);
        attr_done = 1;
    }

    __half *xh, *hA, *hB;
    float *s0, *q0, *s1, *q1, *s2, *q2;
    cudaGetSymbolAddress((void**)&xh, g_xh);
    cudaGetSymbolAddress((void**)&hA, g_hA);
    cudaGetSymbolAddress((void**)&hB, g_hB);
    cudaGetSymbolAddress((void**)&s0, g_s0);
    cudaGetSymbolAddress((void**)&q0, g_q0);
    cudaGetSymbolAddress((void**)&s1, g_s1);
    cudaGetSymbolAddress((void**)&q1, g_q1);
    cudaGetSymbolAddress((void**)&s2, g_s2);
    cudaGetSymbolAddress((void**)&q2, g_q2);

    // K1: full CSR build + convert (internal grid barriers)
    k_csr<<<CSR_BLOCKS, 256>>>(x, ei, N, E, NB, total8);

    // layer 0: xh -> hA (stats -> s0/q0)
    k_gather<0><<<GATHER_BLOCKS, 256>>>(xh, nullptr, nullptr, nullptr, nullptr, invN, N);
    k_gemm<0><<<GEMM_BLOCKS, 256, SMEM_BYTES>>>(xh, hA, Wrel, brel, Wroot,
                                                nullptr, nullptr, nullptr, nullptr,
                                                s0, q0, invN, N);

    // layer 1: hA -> hB (BN from s0; stats -> s1)
    k_gather<1><<<GATHER_BLOCKS, 256>>>(hA, s0, q0, gamma, beta, invN, N);
    k_gemm<1><<<GEMM_BLOCKS, 256, SMEM_BYTES>>>(hA, hB, Wrel + 4096, brel + 64, Wroot + 4096,
                                                s0, q0, gamma, beta,
                                                s1, q1, invN, N);

    // layer 2: hB -> hA (BN from s1; stats -> s2)
    k_gather<1><<<GATHER_BLOCKS, 256>>>(hB, s1, q1, gamma + 64, beta + 64, invN, N);
    k_gemm<1><<<GEMM_BLOCKS, 256, SMEM_BYTES>>>(hB, hA, Wrel + 8192, brel + 128, Wroot + 8192,
                                                s1, q1, gamma + 64, beta + 64,
                                                s2, q2, invN, N);

    // pool (applies layer-2 BN+ReLU from s2/q2) + classifier
    k_pool<<<G, 1024>>>(hA, batch, N, Wcls, bcls,
                        s2, q2, gamma + 128, beta + 128, invN, out);
}